// round 4
// baseline (speedup 1.0000x reference)
#include <cuda_runtime.h>
#include <cuda_bf16.h>
#include <cstdint>

// Problem constants
constexpr int Bb  = 2;
constexpr int Ss  = 2048;
constexpr int Dd  = 1024;
constexpr int Hh  = 16;
constexpr int HDd = 64;

// ---------------------------------------------------------------------------
// Scratch (allocation-free: __device__ globals)
// ---------------------------------------------------------------------------
__device__ float g_q[Bb * Hh * Ss * HDd];    // [B,H,S,HD]
__device__ float g_k[Bb * Hh * Ss * HDd];
__device__ float g_v[Bb * Hh * Ss * HDd];
__device__ float g_ctx[Bb * Ss * Dd];        // [B,S,D]

// Split-bf16 GEMM operands (row-major, K contiguous)
__device__ __nv_bfloat16 a_act[4][2 * 4096 * 1024];
__device__ __nv_bfloat16 b_wt[4][2 * 1024 * 1024];

// Split-bf16 attention operands
__device__ __nv_bfloat16 att_q[2][(size_t)32 * 2048 * 64];   // [bh][s][hd], scale folded
__device__ __nv_bfloat16 att_k[2][(size_t)32 * 2048 * 64];   // [bh][s][hd]
__device__ __nv_bfloat16 att_vt[2][(size_t)32 * 64 * 2048];  // [bh][hd][s]

// ---------------------------------------------------------------------------
// Helpers
// ---------------------------------------------------------------------------
__device__ __forceinline__ uint32_t smem_u32(const void* p) {
    uint32_t a;
    asm("{ .reg .u64 t; cvta.to.shared.u64 t, %1; cvt.u32.u64 %0, t; }"
        : "=r"(a) : "l"(p));
    return a;
}

#define CP16(dst, src) \
    asm volatile("cp.async.cg.shared.global [%0], [%1], 16;" :: "r"(dst), "l"(src))
#define CP_COMMIT() asm volatile("cp.async.commit_group;" ::: "memory")
#define CP_WAIT1()  asm volatile("cp.async.wait_group 1;" ::: "memory")

__device__ __forceinline__ void ldsm4(uint32_t* r, uint32_t addr) {
    asm volatile("ldmatrix.sync.aligned.m8n8.x4.shared.b16 {%0,%1,%2,%3}, [%4];"
        : "=r"(r[0]), "=r"(r[1]), "=r"(r[2]), "=r"(r[3]) : "r"(addr));
}

__device__ __forceinline__ void mma16816(float* c, const uint32_t* a, const uint32_t* b) {
    asm volatile(
        "mma.sync.aligned.m16n8k16.row.col.f32.bf16.bf16.f32 "
        "{%0,%1,%2,%3}, {%4,%5,%6,%7}, {%8,%9}, {%0,%1,%2,%3};"
        : "+f"(c[0]), "+f"(c[1]), "+f"(c[2]), "+f"(c[3])
        : "r"(a[0]), "r"(a[1]), "r"(a[2]), "r"(a[3]), "r"(b[0]), "r"(b[1]));
}

__device__ __forceinline__ uint32_t packbf(float x, float y) {
    __nv_bfloat162 t = __floats2bfloat162_rn(x, y);
    return *(uint32_t*)&t;
}

// ---------------------------------------------------------------------------
// Conversion kernels: fp32 -> hi/lo bf16
// ---------------------------------------------------------------------------
__device__ __forceinline__ void conv8(const float* __restrict__ src,
                                      __nv_bfloat16* __restrict__ hi,
                                      __nv_bfloat16* __restrict__ lo,
                                      size_t base)
{
    float4 f0 = *(const float4*)(src + base);
    float4 f1 = *(const float4*)(src + base + 4);
    float xs[8] = {f0.x, f0.y, f0.z, f0.w, f1.x, f1.y, f1.z, f1.w};
    union { uint4 u4; __nv_bfloat16 h[8]; } H, L;
#pragma unroll
    for (int j = 0; j < 8; j++) {
        __nv_bfloat16 h = __float2bfloat16_rn(xs[j]);
        H.h[j] = h;
        L.h[j] = __float2bfloat16_rn(xs[j] - __bfloat162float(h));
    }
    *(uint4*)(hi + base) = H.u4;
    *(uint4*)(lo + base) = L.u4;
}

__global__ __launch_bounds__(256)
void conv_acts_kernel(const float* __restrict__ q, const float* __restrict__ k,
                      const float* __restrict__ v)
{
    const int z = blockIdx.z;
    const float* src = (z == 0) ? q : (z == 1) ? k : v;
    const size_t base = ((size_t)blockIdx.x * 256 + threadIdx.x) * 8;
    conv8(src, a_act[z], a_act[z] + (size_t)4096 * 1024, base);
}

__global__ __launch_bounds__(256)
void conv_ctx_kernel()
{
    const size_t base = ((size_t)blockIdx.x * 256 + threadIdx.x) * 8;
    conv8(g_ctx, a_act[3], a_act[3] + (size_t)4096 * 1024, base);
}

__global__ __launch_bounds__(256)
void conv_w_kernel(const float* __restrict__ Wq, const float* __restrict__ Wk,
                   const float* __restrict__ Wv, const float* __restrict__ Wo)
{
    const int w = blockIdx.z;
    const float* W = (w == 0) ? Wq : (w == 1) ? Wk : (w == 2) ? Wv : Wo;
    const int k = blockIdx.x;
    __nv_bfloat16* hi = b_wt[w];
    __nv_bfloat16* lo = b_wt[w] + (size_t)1024 * 1024;
#pragma unroll
    for (int j = 0; j < 4; j++) {
        const int n = threadIdx.x * 4 + j;
        const size_t idx = (w < 3)
            ? ((size_t)(n >> 6) << 16) + (size_t)k * 64 + (n & 63)
            : (size_t)k * 1024 + n;
        const float x = W[idx];
        __nv_bfloat16 h = __float2bfloat16_rn(x);
        hi[(size_t)n * 1024 + k] = h;
        lo[(size_t)n * 1024 + k] = __float2bfloat16_rn(x - __bfloat162float(h));
    }
}

// Attention operand prep: q (x0.125) and k -> hi/lo [bh][s][64]; v -> transposed
// hi/lo [bh][hd][s]. Grid (32 s-tiles, 32 bh).
__global__ __launch_bounds__(256)
void conv_attn_kernel()
{
    __shared__ float vs[64][65];
    const int bh = blockIdx.y, st = blockIdx.x, t = threadIdx.x;
    const size_t base = ((size_t)bh * 2048 + st * 64) * 64;

    for (int u = t; u < 1024; u += 256) {
        // q with scale
        {
            float4 f = *(const float4*)(g_q + base + u * 4);
            float xs[4] = {f.x * 0.125f, f.y * 0.125f, f.z * 0.125f, f.w * 0.125f};
            union { uint2 u2; __nv_bfloat16 h[4]; } H, L;
#pragma unroll
            for (int j = 0; j < 4; j++) {
                __nv_bfloat16 h = __float2bfloat16_rn(xs[j]);
                H.h[j] = h;
                L.h[j] = __float2bfloat16_rn(xs[j] - __bfloat162float(h));
            }
            *(uint2*)(att_q[0] + base + u * 4) = H.u2;
            *(uint2*)(att_q[1] + base + u * 4) = L.u2;
        }
        // k
        {
            float4 f = *(const float4*)(g_k + base + u * 4);
            float xs[4] = {f.x, f.y, f.z, f.w};
            union { uint2 u2; __nv_bfloat16 h[4]; } H, L;
#pragma unroll
            for (int j = 0; j < 4; j++) {
                __nv_bfloat16 h = __float2bfloat16_rn(xs[j]);
                H.h[j] = h;
                L.h[j] = __float2bfloat16_rn(xs[j] - __bfloat162float(h));
            }
            *(uint2*)(att_k[0] + base + u * 4) = H.u2;
            *(uint2*)(att_k[1] + base + u * 4) = L.u2;
        }
        // v -> smem
        {
            const int s = u >> 4, hd = (u & 15) * 4;
            float4 f = *(const float4*)(g_v + base + (size_t)s * 64 + hd);
            vs[s][hd] = f.x; vs[s][hd + 1] = f.y; vs[s][hd + 2] = f.z; vs[s][hd + 3] = f.w;
        }
    }
    __syncthreads();
    // transpose out: thread writes 4 s-values for one hd row
    for (int u = t; u < 1024; u += 256) {
        const int hd = u >> 4, s0 = (u & 15) * 4;
        union { uint2 u2; __nv_bfloat16 h[4]; } H, L;
#pragma unroll
        for (int j = 0; j < 4; j++) {
            const float x = vs[s0 + j][hd];
            __nv_bfloat16 h = __float2bfloat16_rn(x);
            H.h[j] = h;
            L.h[j] = __float2bfloat16_rn(x - __bfloat162float(h));
        }
        const size_t o = ((size_t)bh * 64 + hd) * 2048 + st * 64 + s0;
        *(uint2*)(att_vt[0] + o) = H.u2;
        *(uint2*)(att_vt[1] + o) = L.u2;
    }
}

// ---------------------------------------------------------------------------
// mma.sync bf16 GEMM (unchanged from R3)
// ---------------------------------------------------------------------------
template<bool SCATTER>
__device__ __forceinline__ void gemm_core(const __nv_bfloat16* __restrict__ At,
                                          const __nv_bfloat16* __restrict__ Bt,
                                          const float* __restrict__ bias,
                                          float* __restrict__ C,
                                          int mt, int nt)
{
    __shared__ __align__(16) __nv_bfloat16 As[2][128][40];
    __shared__ __align__(16) __nv_bfloat16 Bs[2][128][40];

    const int tid = threadIdx.x, lane = tid & 31, wid = tid >> 5;
    const int wm = wid & 1, wn = wid >> 1;

    float acc[4][4][4] = {};

    const int ar  = tid >> 1;
    const int ac0 = (tid & 1) * 2;
    const __nv_bfloat16* Abase = At + (size_t)(mt * 128 + ar) * 1024;
    const __nv_bfloat16* Bbase = Bt + (size_t)(nt * 128 + ar) * 1024;

    const uint32_t sAs = smem_u32(As);
    const uint32_t sBs = smem_u32(Bs);
    const uint32_t dA = sAs + ar * 80 + ac0 * 16;
    const uint32_t dB = sBs + ar * 80 + ac0 * 16;

    const uint32_t a_row = wm * 64 + (lane & 15);
    const uint32_t a_col = (lane >> 4) << 3;
    const uint32_t b_row = wn * 32 + (lane & 7) + ((lane >> 4) << 3);
    const uint32_t b_col = ((lane >> 3) & 1) << 3;

#define ISSUE(kt) do {                                                        \
    const int _kt = (kt);                                                     \
    const int _seg = _kt >> 5, _kk = _kt & 31;                                \
    const int _as = _seg >> 1, _bs = _seg & 1;                                \
    const __nv_bfloat16* _a = Abase + (size_t)_as * 4096 * 1024 + _kk * 32 + ac0 * 8; \
    const __nv_bfloat16* _b = Bbase + (size_t)_bs * 1024 * 1024 + _kk * 32 + ac0 * 8; \
    const uint32_t _da = dA + (_kt & 1) * 10240;                              \
    const uint32_t _db = dB + (_kt & 1) * 10240;                              \
    CP16(_da, _a); CP16(_da + 16, _a + 8);                                    \
    CP16(_db, _b); CP16(_db + 16, _b + 8);                                    \
    CP_COMMIT();                                                              \
} while (0)

    ISSUE(0);
    ISSUE(1);

    for (int kt = 0; kt < 96; kt++) {
        CP_WAIT1();
        __syncthreads();

        const uint32_t sa = sAs + (kt & 1) * 10240;
        const uint32_t sb = sBs + (kt & 1) * 10240;
#pragma unroll
        for (int ks = 0; ks < 32; ks += 16) {
            uint32_t af[4][4], bf[2][4];
#pragma unroll
            for (int mi = 0; mi < 4; mi++)
                ldsm4(af[mi], sa + ((a_row + mi * 16) * 40 + ks + a_col) * 2);
#pragma unroll
            for (int nj2 = 0; nj2 < 2; nj2++)
                ldsm4(bf[nj2], sb + ((b_row + nj2 * 16) * 40 + ks + b_col) * 2);
#pragma unroll
            for (int mi = 0; mi < 4; mi++)
#pragma unroll
                for (int nj = 0; nj < 4; nj++)
                    mma16816(acc[mi][nj], af[mi], &bf[nj >> 1][(nj & 1) * 2]);
        }
        __syncthreads();

        if (kt + 2 < 96) ISSUE(kt + 2);
        else CP_COMMIT();
    }
#undef ISSUE

#pragma unroll
    for (int mi = 0; mi < 4; mi++) {
        const int r0 = mt * 128 + wm * 64 + mi * 16 + (lane >> 2);
#pragma unroll
        for (int nj = 0; nj < 4; nj++) {
            const int col = nt * 128 + wn * 32 + nj * 8 + ((lane & 3) << 1);
            const float b0 = bias[col], b1 = bias[col + 1];
            float2 v0 = {acc[mi][nj][0] + b0, acc[mi][nj][1] + b1};
            float2 v1 = {acc[mi][nj][2] + b0, acc[mi][nj][3] + b1};
            if (SCATTER) {
                const int h = col >> 6, hd = col & 63;
                const int b_0 = r0 >> 11, s0 = r0 & 2047;
                const int b_1 = (r0 + 8) >> 11, s1 = (r0 + 8) & 2047;
                *(float2*)(C + ((size_t)((b_0 * 16 + h) * 2048 + s0)) * 64 + hd) = v0;
                *(float2*)(C + ((size_t)((b_1 * 16 + h) * 2048 + s1)) * 64 + hd) = v1;
            } else {
                *(float2*)(C + (size_t)r0 * 1024 + col) = v0;
                *(float2*)(C + (size_t)(r0 + 8) * 1024 + col) = v1;
            }
        }
    }
}

__global__ __launch_bounds__(256, 2)
void qkv_gemm_kernel(const float* __restrict__ bq, const float* __restrict__ bk,
                     const float* __restrict__ bv)
{
    const int z = blockIdx.z;
    const float* bias = (z == 0) ? bq : (z == 1) ? bk : bv;
    float* C = (z == 0) ? g_q : (z == 1) ? g_k : g_v;
    gemm_core<true>(a_act[z], b_wt[z], bias, C, blockIdx.y, blockIdx.x);
}

__global__ __launch_bounds__(256, 2)
void oproj_gemm_kernel(const float* __restrict__ bo, float* __restrict__ out)
{
    gemm_core<false>(a_act[3], b_wt[3], bo, out, blockIdx.y, blockIdx.x);
}

// ---------------------------------------------------------------------------
// Tensor-core flash attention.
// Grid (16 q-tiles, 32 bh), 256 threads (8 warps). Q tile 128x64 in register
// fragments (warp = 16 rows). KV tile 64, double-buffered cp.async.
// Split-bf16 3-pass for both S = Q K^T and O += P V.
// smem layout (bf16, row stride 72): per buffer: KH, KL, VH, VL each [64][72].
// ---------------------------------------------------------------------------
constexpr int ATW = 72;                                   // padded row (144 B)
constexpr int ATT_SMEM = 2 * 4 * 64 * ATW * 2;            // 73728 B

__global__ __launch_bounds__(256)
void attn_tc_kernel()
{
    extern __shared__ __nv_bfloat16 smb[];
    const uint32_t sb = smem_u32(smb);
    const int tid = threadIdx.x, lane = tid & 31, w = tid >> 5;
    const int bh = blockIdx.y;
    const int q0 = blockIdx.x * 128;

    // ---- Q fragments (staged through smem) ----
    uint32_t qh[4][4], ql[4][4];
    {
        const uint32_t a_base = sb + (((w * 16 + (lane & 15)) * ATW + ((lane >> 4) << 3)) << 1);
#pragma unroll
        for (int seg = 0; seg < 2; seg++) {
            const __nv_bfloat16* src = att_q[seg] + ((size_t)bh * 2048 + q0) * 64;
            for (int u = tid; u < 1024; u += 256) {
                const int r = u >> 3, c = (u & 7) * 8;
                *(uint4*)(smb + r * ATW + c) = *(const uint4*)(src + (size_t)r * 64 + c);
            }
            __syncthreads();
#pragma unroll
            for (int kk = 0; kk < 4; kk++)
                ldsm4(seg ? ql[kk] : qh[kk], a_base + kk * 32);
            __syncthreads();
        }
    }

    // ---- KV pipeline source/dst for this thread ----
    const int arr = tid >> 6;          // 0:KH 1:KL 2:VH 3:VL
    const int rr0 = tid & 63;
    const __nv_bfloat16* src0;
    size_t step;
    if (arr < 2) { src0 = att_k[arr]     + ((size_t)bh * 2048 + rr0) * 64; step = 4096; }
    else         { src0 = att_vt[arr - 2] + ((size_t)bh * 64 + rr0) * 2048; step = 64;   }
    const uint32_t dst0 = sb + arr * 9216 + rr0 * 144;

#define AISSUE(it) do {                                                       \
    const __nv_bfloat16* _s = src0 + (size_t)(it) * step;                     \
    const uint32_t _d = dst0 + ((it) & 1) * 36864;                            \
    CP16(_d,       _s);      CP16(_d + 16,  _s + 8);                          \
    CP16(_d + 32,  _s + 16); CP16(_d + 48,  _s + 24);                         \
    CP16(_d + 64,  _s + 32); CP16(_d + 80,  _s + 40);                         \
    CP16(_d + 96,  _s + 48); CP16(_d + 112, _s + 56);                         \
    CP_COMMIT();                                                              \
} while (0)

    AISSUE(0);
    AISSUE(1);

    // ldmatrix B addressing
    const uint32_t brow = (lane & 7) + ((lane >> 4) << 3);
    const uint32_t bcol2 = (((lane >> 3) & 1) << 3) * 2;

    float o[8][4] = {};
    float m0 = -1e30f, m1 = -1e30f, l0 = 0.0f, l1 = 0.0f;

    for (int it = 0; it < 32; it++) {
        CP_WAIT1();
        __syncthreads();

        const uint32_t bufb = sb + (it & 1) * 36864;
        const uint32_t KH = bufb, KL = bufb + 9216, VH = bufb + 18432, VL = bufb + 27648;

        // ---- S = qhi*khi + qlo*khi + qhi*klo ----
        float s[8][4] = {};
#pragma unroll
        for (int p = 0; p < 3; p++) {
            const uint32_t (*A)[4] = (p == 1) ? ql : qh;
            const uint32_t kb = (p == 2) ? KL : KH;
#pragma unroll
            for (int kk = 0; kk < 4; kk++)
#pragma unroll
                for (int g = 0; g < 4; g++) {
                    uint32_t bf[4];
                    ldsm4(bf, kb + (g * 16 + brow) * 144 + kk * 32 + bcol2);
                    mma16816(s[2 * g],     A[kk], bf);
                    mma16816(s[2 * g + 1], A[kk], bf + 2);
                }
        }

        // ---- online softmax (rows r = lane>>2 and r+8, stats in quad) ----
        float mx0 = -1e30f, mx1 = -1e30f;
#pragma unroll
        for (int nj = 0; nj < 8; nj++) {
            mx0 = fmaxf(mx0, fmaxf(s[nj][0], s[nj][1]));
            mx1 = fmaxf(mx1, fmaxf(s[nj][2], s[nj][3]));
        }
        mx0 = fmaxf(mx0, __shfl_xor_sync(0xffffffffu, mx0, 1));
        mx0 = fmaxf(mx0, __shfl_xor_sync(0xffffffffu, mx0, 2));
        mx1 = fmaxf(mx1, __shfl_xor_sync(0xffffffffu, mx1, 1));
        mx1 = fmaxf(mx1, __shfl_xor_sync(0xffffffffu, mx1, 2));
        const float mn0 = fmaxf(m0, mx0), mn1 = fmaxf(m1, mx1);
        const float f0 = __expf(m0 - mn0), f1 = __expf(m1 - mn1);
        m0 = mn0; m1 = mn1;

        uint32_t ph[4][4], pl[4][4];
        float la0 = 0.0f, la1 = 0.0f;
#pragma unroll
        for (int nj = 0; nj < 8; nj++) {
            float pe[4], pel[4];
#pragma unroll
            for (int e = 0; e < 4; e++) {
                const float p = __expf(s[nj][e] - ((e < 2) ? mn0 : mn1));
                if (e < 2) la0 += p; else la1 += p;
                const __nv_bfloat16 hb = __float2bfloat16_rn(p);
                pe[e]  = p;
                pel[e] = p - __bfloat162float(hb);
            }
            const int kk = nj >> 1, sel = (nj & 1) * 2;
            ph[kk][sel]     = packbf(pe[0], pe[1]);
            ph[kk][sel + 1] = packbf(pe[2], pe[3]);
            pl[kk][sel]     = packbf(pel[0], pel[1]);
            pl[kk][sel + 1] = packbf(pel[2], pel[3]);
        }
        la0 += __shfl_xor_sync(0xffffffffu, la0, 1);
        la0 += __shfl_xor_sync(0xffffffffu, la0, 2);
        la1 += __shfl_xor_sync(0xffffffffu, la1, 1);
        la1 += __shfl_xor_sync(0xffffffffu, la1, 2);
        l0 = l0 * f0 + la0;
        l1 = l1 * f1 + la1;
#pragma unroll
        for (int nj = 0; nj < 8; nj++) {
            o[nj][0] *= f0; o[nj][1] *= f0;
            o[nj][2] *= f1; o[nj][3] *= f1;
        }

        // ---- O += phi*vhi + phi*vlo + plo*vhi ----
#pragma unroll
        for (int p = 0; p < 3; p++) {
            const uint32_t (*A)[4] = (p == 2) ? pl : ph;
            const uint32_t vb = (p == 1) ? VL : VH;
#pragma unroll
            for (int kk = 0; kk < 4; kk++)
#pragma unroll
                for (int g = 0; g < 4; g++) {
                    uint32_t bf[4];
                    ldsm4(bf, vb + (g * 16 + brow) * 144 + kk * 32 + bcol2);
                    mma16816(o[2 * g],     A[kk], bf);
                    mma16816(o[2 * g + 1], A[kk], bf + 2);
                }
        }

        __syncthreads();
        if (it + 2 < 32) AISSUE(it + 2);
        else CP_COMMIT();
    }
#undef AISSUE

    // ---- epilogue ----
    const int b = bh >> 4, h = bh & 15;
    const float inv0 = 1.0f / l0, inv1 = 1.0f / l1;
    const int row0 = q0 + w * 16 + (lane >> 2);
#pragma unroll
    for (int nj = 0; nj < 8; nj++) {
        const int col = h * 64 + nj * 8 + ((lane & 3) << 1);
        float2 v0 = {o[nj][0] * inv0, o[nj][1] * inv0};
        float2 v1 = {o[nj][2] * inv1, o[nj][3] * inv1};
        *(float2*)(g_ctx + ((size_t)(b * 2048 + row0)) * 1024 + col) = v0;
        *(float2*)(g_ctx + ((size_t)(b * 2048 + row0 + 8)) * 1024 + col) = v1;
    }
}

// ---------------------------------------------------------------------------
extern "C" void kernel_launch(void* const* d_in, const int* in_sizes, int n_in,
                              void* d_out, int out_size)
{
    (void)in_sizes; (void)n_in; (void)out_size;
    const float* q  = (const float*)d_in[0];
    const float* k  = (const float*)d_in[1];
    const float* v  = (const float*)d_in[2];
    const float* Wq = (const float*)d_in[3];
    const float* bq = (const float*)d_in[4];
    const float* Wk = (const float*)d_in[5];
    const float* bk = (const float*)d_in[6];
    const float* Wv = (const float*)d_in[7];
    const float* bv = (const float*)d_in[8];
    const float* Wo = (const float*)d_in[9];
    const float* bo = (const float*)d_in[10];
    float* out = (float*)d_out;

    cudaFuncSetAttribute(attn_tc_kernel, cudaFuncAttributeMaxDynamicSharedMemorySize,
                         ATT_SMEM);

    // Convert weights + activations to split-bf16
    conv_w_kernel<<<dim3(1024, 1, 4), 256>>>(Wq, Wk, Wv, Wo);
    conv_acts_kernel<<<dim3(2048, 1, 3), 256>>>(q, k, v);

    // QKV projections on tensor cores
    qkv_gemm_kernel<<<dim3(8, 32, 3), 256>>>(bq, bk, bv);

    // Attention operand prep + tensor-core flash attention
    conv_attn_kernel<<<dim3(32, 32), 256>>>();
    attn_tc_kernel<<<dim3(16, 32), 256, ATT_SMEM>>>();

    // Output projection on tensor cores
    conv_ctx_kernel<<<2048, 256>>>();
    oproj_gemm_kernel<<<dim3(8, 32), 256>>>(bo, out);
}

// round 5
// speedup vs baseline: 1.5725x; 1.5725x over previous
#include <cuda_runtime.h>
#include <cuda_bf16.h>
#include <cstdint>

// Problem constants
constexpr int Bb  = 2;
constexpr int Ss  = 2048;
constexpr int Dd  = 1024;
constexpr int Hh  = 16;
constexpr int HDd = 64;

// ---------------------------------------------------------------------------
// Scratch (allocation-free: __device__ globals)
// ---------------------------------------------------------------------------
__device__ float g_q[Bb * Hh * Ss * HDd];    // [B,H,S,HD]
__device__ float g_k[Bb * Hh * Ss * HDd];
__device__ float g_v[Bb * Hh * Ss * HDd];
__device__ float g_ctx[Bb * Ss * Dd];        // [B,S,D]

// Split-bf16 GEMM operands (row-major, K contiguous)
__device__ __nv_bfloat16 a_act[4][2 * 4096 * 1024];
__device__ __nv_bfloat16 b_wt[4][2 * 1024 * 1024];

// Split-bf16 attention operands
__device__ __nv_bfloat16 att_q[2][(size_t)32 * 2048 * 64];   // [bh][s][hd], scale folded
__device__ __nv_bfloat16 att_k[2][(size_t)32 * 2048 * 64];   // [bh][s][hd]
__device__ __nv_bfloat16 att_vt[2][(size_t)32 * 64 * 2048];  // [bh][hd][s]

// ---------------------------------------------------------------------------
// Helpers
// ---------------------------------------------------------------------------
__device__ __forceinline__ uint32_t smem_u32(const void* p) {
    uint32_t a;
    asm("{ .reg .u64 t; cvta.to.shared.u64 t, %1; cvt.u32.u64 %0, t; }"
        : "=r"(a) : "l"(p));
    return a;
}

#define CP16(dst, src) \
    asm volatile("cp.async.cg.shared.global [%0], [%1], 16;" :: "r"(dst), "l"(src))
#define CP_COMMIT() asm volatile("cp.async.commit_group;" ::: "memory")
#define CP_WAIT1()  asm volatile("cp.async.wait_group 1;" ::: "memory")

__device__ __forceinline__ void ldsm4(uint32_t* r, uint32_t addr) {
    asm volatile("ldmatrix.sync.aligned.m8n8.x4.shared.b16 {%0,%1,%2,%3}, [%4];"
        : "=r"(r[0]), "=r"(r[1]), "=r"(r[2]), "=r"(r[3]) : "r"(addr));
}

__device__ __forceinline__ void mma16816(float* c, const uint32_t* a, const uint32_t* b) {
    asm volatile(
        "mma.sync.aligned.m16n8k16.row.col.f32.bf16.bf16.f32 "
        "{%0,%1,%2,%3}, {%4,%5,%6,%7}, {%8,%9}, {%0,%1,%2,%3};"
        : "+f"(c[0]), "+f"(c[1]), "+f"(c[2]), "+f"(c[3])
        : "r"(a[0]), "r"(a[1]), "r"(a[2]), "r"(a[3]), "r"(b[0]), "r"(b[1]));
}

__device__ __forceinline__ uint32_t packbf(float x, float y) {
    __nv_bfloat162 t = __floats2bfloat162_rn(x, y);
    return *(uint32_t*)&t;
}

// ---------------------------------------------------------------------------
// Conversion kernels: fp32 -> hi/lo bf16
// ---------------------------------------------------------------------------
__device__ __forceinline__ void conv8(const float* __restrict__ src,
                                      __nv_bfloat16* __restrict__ hi,
                                      __nv_bfloat16* __restrict__ lo,
                                      size_t base)
{
    float4 f0 = *(const float4*)(src + base);
    float4 f1 = *(const float4*)(src + base + 4);
    float xs[8] = {f0.x, f0.y, f0.z, f0.w, f1.x, f1.y, f1.z, f1.w};
    union { uint4 u4; __nv_bfloat16 h[8]; } H, L;
#pragma unroll
    for (int j = 0; j < 8; j++) {
        __nv_bfloat16 h = __float2bfloat16_rn(xs[j]);
        H.h[j] = h;
        L.h[j] = __float2bfloat16_rn(xs[j] - __bfloat162float(h));
    }
    *(uint4*)(hi + base) = H.u4;
    *(uint4*)(lo + base) = L.u4;
}

__global__ __launch_bounds__(256)
void conv_acts_kernel(const float* __restrict__ q, const float* __restrict__ k,
                      const float* __restrict__ v)
{
    const int z = blockIdx.z;
    const float* src = (z == 0) ? q : (z == 1) ? k : v;
    const size_t base = ((size_t)blockIdx.x * 256 + threadIdx.x) * 8;
    conv8(src, a_act[z], a_act[z] + (size_t)4096 * 1024, base);
}

__global__ __launch_bounds__(256)
void conv_ctx_kernel()
{
    const size_t base = ((size_t)blockIdx.x * 256 + threadIdx.x) * 8;
    conv8(g_ctx, a_act[3], a_act[3] + (size_t)4096 * 1024, base);
}

__global__ __launch_bounds__(256)
void conv_w_kernel(const float* __restrict__ Wq, const float* __restrict__ Wk,
                   const float* __restrict__ Wv, const float* __restrict__ Wo)
{
    const int w = blockIdx.z;
    const float* W = (w == 0) ? Wq : (w == 1) ? Wk : (w == 2) ? Wv : Wo;
    const int k = blockIdx.x;
    __nv_bfloat16* hi = b_wt[w];
    __nv_bfloat16* lo = b_wt[w] + (size_t)1024 * 1024;
#pragma unroll
    for (int j = 0; j < 4; j++) {
        const int n = threadIdx.x * 4 + j;
        const size_t idx = (w < 3)
            ? ((size_t)(n >> 6) << 16) + (size_t)k * 64 + (n & 63)
            : (size_t)k * 1024 + n;
        const float x = W[idx];
        __nv_bfloat16 h = __float2bfloat16_rn(x);
        hi[(size_t)n * 1024 + k] = h;
        lo[(size_t)n * 1024 + k] = __float2bfloat16_rn(x - __bfloat162float(h));
    }
}

// Attention operand prep: q (x0.125) and k -> hi/lo [bh][s][64]; v -> transposed
// hi/lo [bh][hd][s]. Grid (32 s-tiles, 32 bh).
__global__ __launch_bounds__(256)
void conv_attn_kernel()
{
    __shared__ float vs[64][65];
    const int bh = blockIdx.y, st = blockIdx.x, t = threadIdx.x;
    const size_t base = ((size_t)bh * 2048 + st * 64) * 64;

    for (int u = t; u < 1024; u += 256) {
        {
            float4 f = *(const float4*)(g_q + base + u * 4);
            float xs[4] = {f.x * 0.125f, f.y * 0.125f, f.z * 0.125f, f.w * 0.125f};
            union { uint2 u2; __nv_bfloat16 h[4]; } H, L;
#pragma unroll
            for (int j = 0; j < 4; j++) {
                __nv_bfloat16 h = __float2bfloat16_rn(xs[j]);
                H.h[j] = h;
                L.h[j] = __float2bfloat16_rn(xs[j] - __bfloat162float(h));
            }
            *(uint2*)(att_q[0] + base + u * 4) = H.u2;
            *(uint2*)(att_q[1] + base + u * 4) = L.u2;
        }
        {
            float4 f = *(const float4*)(g_k + base + u * 4);
            float xs[4] = {f.x, f.y, f.z, f.w};
            union { uint2 u2; __nv_bfloat16 h[4]; } H, L;
#pragma unroll
            for (int j = 0; j < 4; j++) {
                __nv_bfloat16 h = __float2bfloat16_rn(xs[j]);
                H.h[j] = h;
                L.h[j] = __float2bfloat16_rn(xs[j] - __bfloat162float(h));
            }
            *(uint2*)(att_k[0] + base + u * 4) = H.u2;
            *(uint2*)(att_k[1] + base + u * 4) = L.u2;
        }
        {
            const int s = u >> 4, hd = (u & 15) * 4;
            float4 f = *(const float4*)(g_v + base + (size_t)s * 64 + hd);
            vs[s][hd] = f.x; vs[s][hd + 1] = f.y; vs[s][hd + 2] = f.z; vs[s][hd + 3] = f.w;
        }
    }
    __syncthreads();
    for (int u = t; u < 1024; u += 256) {
        const int hd = u >> 4, s0 = (u & 15) * 4;
        union { uint2 u2; __nv_bfloat16 h[4]; } H, L;
#pragma unroll
        for (int j = 0; j < 4; j++) {
            const float x = vs[s0 + j][hd];
            __nv_bfloat16 h = __float2bfloat16_rn(x);
            H.h[j] = h;
            L.h[j] = __float2bfloat16_rn(x - __bfloat162float(h));
        }
        const size_t o = ((size_t)bh * 64 + hd) * 2048 + st * 64 + s0;
        *(uint2*)(att_vt[0] + o) = H.u2;
        *(uint2*)(att_vt[1] + o) = L.u2;
    }
}

// ---------------------------------------------------------------------------
// mma.sync bf16 GEMM (unchanged from R3 — known good, 234 TF/s)
// ---------------------------------------------------------------------------
template<bool SCATTER>
__device__ __forceinline__ void gemm_core(const __nv_bfloat16* __restrict__ At,
                                          const __nv_bfloat16* __restrict__ Bt,
                                          const float* __restrict__ bias,
                                          float* __restrict__ C,
                                          int mt, int nt)
{
    __shared__ __align__(16) __nv_bfloat16 As[2][128][40];
    __shared__ __align__(16) __nv_bfloat16 Bs[2][128][40];

    const int tid = threadIdx.x, lane = tid & 31, wid = tid >> 5;
    const int wm = wid & 1, wn = wid >> 1;

    float acc[4][4][4] = {};

    const int ar  = tid >> 1;
    const int ac0 = (tid & 1) * 2;
    const __nv_bfloat16* Abase = At + (size_t)(mt * 128 + ar) * 1024;
    const __nv_bfloat16* Bbase = Bt + (size_t)(nt * 128 + ar) * 1024;

    const uint32_t sAs = smem_u32(As);
    const uint32_t sBs = smem_u32(Bs);
    const uint32_t dA = sAs + ar * 80 + ac0 * 16;
    const uint32_t dB = sBs + ar * 80 + ac0 * 16;

    const uint32_t a_row = wm * 64 + (lane & 15);
    const uint32_t a_col = (lane >> 4) << 3;
    const uint32_t b_row = wn * 32 + (lane & 7) + ((lane >> 4) << 3);
    const uint32_t b_col = ((lane >> 3) & 1) << 3;

#define ISSUE(kt) do {                                                        \
    const int _kt = (kt);                                                     \
    const int _seg = _kt >> 5, _kk = _kt & 31;                                \
    const int _as = _seg >> 1, _bs = _seg & 1;                                \
    const __nv_bfloat16* _a = Abase + (size_t)_as * 4096 * 1024 + _kk * 32 + ac0 * 8; \
    const __nv_bfloat16* _b = Bbase + (size_t)_bs * 1024 * 1024 + _kk * 32 + ac0 * 8; \
    const uint32_t _da = dA + (_kt & 1) * 10240;                              \
    const uint32_t _db = dB + (_kt & 1) * 10240;                              \
    CP16(_da, _a); CP16(_da + 16, _a + 8);                                    \
    CP16(_db, _b); CP16(_db + 16, _b + 8);                                    \
    CP_COMMIT();                                                              \
} while (0)

    ISSUE(0);
    ISSUE(1);

    for (int kt = 0; kt < 96; kt++) {
        CP_WAIT1();
        __syncthreads();

        const uint32_t sa = sAs + (kt & 1) * 10240;
        const uint32_t sb = sBs + (kt & 1) * 10240;
#pragma unroll
        for (int ks = 0; ks < 32; ks += 16) {
            uint32_t af[4][4], bf[2][4];
#pragma unroll
            for (int mi = 0; mi < 4; mi++)
                ldsm4(af[mi], sa + ((a_row + mi * 16) * 40 + ks + a_col) * 2);
#pragma unroll
            for (int nj2 = 0; nj2 < 2; nj2++)
                ldsm4(bf[nj2], sb + ((b_row + nj2 * 16) * 40 + ks + b_col) * 2);
#pragma unroll
            for (int mi = 0; mi < 4; mi++)
#pragma unroll
                for (int nj = 0; nj < 4; nj++)
                    mma16816(acc[mi][nj], af[mi], &bf[nj >> 1][(nj & 1) * 2]);
        }
        __syncthreads();

        if (kt + 2 < 96) ISSUE(kt + 2);
        else CP_COMMIT();
    }
#undef ISSUE

#pragma unroll
    for (int mi = 0; mi < 4; mi++) {
        const int r0 = mt * 128 + wm * 64 + mi * 16 + (lane >> 2);
#pragma unroll
        for (int nj = 0; nj < 4; nj++) {
            const int col = nt * 128 + wn * 32 + nj * 8 + ((lane & 3) << 1);
            const float b0 = bias[col], b1 = bias[col + 1];
            float2 v0 = {acc[mi][nj][0] + b0, acc[mi][nj][1] + b1};
            float2 v1 = {acc[mi][nj][2] + b0, acc[mi][nj][3] + b1};
            if (SCATTER) {
                const int h = col >> 6, hd = col & 63;
                const int b_0 = r0 >> 11, s0 = r0 & 2047;
                const int b_1 = (r0 + 8) >> 11, s1 = (r0 + 8) & 2047;
                *(float2*)(C + ((size_t)((b_0 * 16 + h) * 2048 + s0)) * 64 + hd) = v0;
                *(float2*)(C + ((size_t)((b_1 * 16 + h) * 2048 + s1)) * 64 + hd) = v1;
            } else {
                *(float2*)(C + (size_t)r0 * 1024 + col) = v0;
                *(float2*)(C + (size_t)(r0 + 8) * 1024 + col) = v1;
            }
        }
    }
}

__global__ __launch_bounds__(256, 2)
void qkv_gemm_kernel(const float* __restrict__ bq, const float* __restrict__ bk,
                     const float* __restrict__ bv)
{
    const int z = blockIdx.z;
    const float* bias = (z == 0) ? bq : (z == 1) ? bk : bv;
    float* C = (z == 0) ? g_q : (z == 1) ? g_k : g_v;
    gemm_core<true>(a_act[z], b_wt[z], bias, C, blockIdx.y, blockIdx.x);
}

__global__ __launch_bounds__(256, 2)
void oproj_gemm_kernel(const float* __restrict__ bo, float* __restrict__ out)
{
    gemm_core<false>(a_act[3], b_wt[3], bo, out, blockIdx.y, blockIdx.x);
}

// ---------------------------------------------------------------------------
// Tensor-core flash attention, v2.
// Grid (8 q-tiles, 32 bh), 256 threads (8 warps). Q tile 256 rows; each warp
// owns 32 rows = 2 m16 fragments, so every K/V ldmatrix feeds 4 MMAs.
// KV tile 64, double-buffered cp.async. Split-bf16 3-pass on both matmuls.
// __launch_bounds__(256,1): full 255-reg budget, no spills.
// ---------------------------------------------------------------------------
constexpr int ATW = 72;                                   // padded row (144 B)
constexpr int ATT_SMEM = 2 * 4 * 64 * ATW * 2;            // 73728 B

__global__ __launch_bounds__(256, 1)
void attn_tc_kernel()
{
    extern __shared__ __nv_bfloat16 smb[];
    const uint32_t sb = smem_u32(smb);
    const int tid = threadIdx.x, lane = tid & 31, w = tid >> 5;
    const int bh = blockIdx.y;
    const int q0 = blockIdx.x * 256;

    // ---- Q fragments: warp w owns rows q0 + w*32 .. +31 (2 m16 frags) ----
    uint32_t qh[2][4][4], ql[2][4][4];
    {
        const int chunk = w >> 2;            // which 128-row stage this warp reads
        const int wrow  = (w & 3) * 32;      // warp's row base within the stage
#pragma unroll
        for (int seg = 0; seg < 2; seg++) {
#pragma unroll
            for (int c = 0; c < 2; c++) {
                const __nv_bfloat16* src = att_q[seg] + ((size_t)bh * 2048 + q0 + c * 128) * 64;
                for (int u = tid; u < 1024; u += 256) {
                    const int r = u >> 3, col = (u & 7) * 8;
                    *(uint4*)(smb + r * ATW + col) = *(const uint4*)(src + (size_t)r * 64 + col);
                }
                __syncthreads();
                if (chunk == c) {
#pragma unroll
                    for (int mi = 0; mi < 2; mi++) {
                        const uint32_t ab = sb +
                            (((wrow + mi * 16 + (lane & 15)) * ATW + ((lane >> 4) << 3)) << 1);
#pragma unroll
                        for (int kk = 0; kk < 4; kk++)
                            ldsm4(seg ? ql[mi][kk] : qh[mi][kk], ab + kk * 32);
                    }
                }
                __syncthreads();
            }
        }
    }

    // ---- KV pipeline ----
    const int arr = tid >> 6;          // 0:KH 1:KL 2:VH 3:VL
    const int rr0 = tid & 63;
    const __nv_bfloat16* src0;
    size_t step;
    if (arr < 2) { src0 = att_k[arr]      + ((size_t)bh * 2048 + rr0) * 64;  step = 4096; }
    else         { src0 = att_vt[arr - 2] + ((size_t)bh * 64 + rr0) * 2048;  step = 64;   }
    const uint32_t dst0 = sb + arr * 9216 + rr0 * 144;

#define AISSUE(it) do {                                                       \
    const __nv_bfloat16* _s = src0 + (size_t)(it) * step;                     \
    const uint32_t _d = dst0 + ((it) & 1) * 36864;                            \
    CP16(_d,       _s);      CP16(_d + 16,  _s + 8);                          \
    CP16(_d + 32,  _s + 16); CP16(_d + 48,  _s + 24);                         \
    CP16(_d + 64,  _s + 32); CP16(_d + 80,  _s + 40);                         \
    CP16(_d + 96,  _s + 48); CP16(_d + 112, _s + 56);                         \
    CP_COMMIT();                                                              \
} while (0)

    AISSUE(0);
    AISSUE(1);

    const uint32_t brow  = (lane & 7) + ((lane >> 4) << 3);
    const uint32_t bcol2 = (((lane >> 3) & 1) << 3) * 2;

    float o[2][8][4] = {};
    float m[2][2], l[2][2];
#pragma unroll
    for (int mi = 0; mi < 2; mi++) { m[mi][0] = m[mi][1] = -1e30f; l[mi][0] = l[mi][1] = 0.0f; }

    for (int it = 0; it < 32; it++) {
        CP_WAIT1();
        __syncthreads();

        const uint32_t bufb = sb + (it & 1) * 36864;
        const uint32_t KH = bufb, KL = bufb + 9216, VH = bufb + 18432, VL = bufb + 27648;

        // ---- S = qhi*khi + qlo*khi + qhi*klo (B fragment reused for 4 MMAs) ----
        float s[2][8][4] = {};
#pragma unroll
        for (int p = 0; p < 3; p++) {
            const uint32_t kb = (p == 2) ? KL : KH;
#pragma unroll
            for (int kk = 0; kk < 4; kk++)
#pragma unroll
                for (int g = 0; g < 4; g++) {
                    uint32_t bf[4];
                    ldsm4(bf, kb + (g * 16 + brow) * 144 + kk * 32 + bcol2);
#pragma unroll
                    for (int mi = 0; mi < 2; mi++) {
                        const uint32_t* A = (p == 1) ? ql[mi][kk] : qh[mi][kk];
                        mma16816(s[mi][2 * g],     A, bf);
                        mma16816(s[mi][2 * g + 1], A, bf + 2);
                    }
                }
        }

        // ---- online softmax + P repack (s consumed in place) ----
        uint32_t ph[2][4][4], pl[2][4][4];
#pragma unroll
        for (int mi = 0; mi < 2; mi++) {
            float mx0 = -1e30f, mx1 = -1e30f;
#pragma unroll
            for (int nj = 0; nj < 8; nj++) {
                mx0 = fmaxf(mx0, fmaxf(s[mi][nj][0], s[mi][nj][1]));
                mx1 = fmaxf(mx1, fmaxf(s[mi][nj][2], s[mi][nj][3]));
            }
            mx0 = fmaxf(mx0, __shfl_xor_sync(0xffffffffu, mx0, 1));
            mx0 = fmaxf(mx0, __shfl_xor_sync(0xffffffffu, mx0, 2));
            mx1 = fmaxf(mx1, __shfl_xor_sync(0xffffffffu, mx1, 1));
            mx1 = fmaxf(mx1, __shfl_xor_sync(0xffffffffu, mx1, 2));
            const float mn0 = fmaxf(m[mi][0], mx0), mn1 = fmaxf(m[mi][1], mx1);
            const float f0 = __expf(m[mi][0] - mn0), f1 = __expf(m[mi][1] - mn1);
            m[mi][0] = mn0; m[mi][1] = mn1;

            float la0 = 0.0f, la1 = 0.0f;
#pragma unroll
            for (int nj = 0; nj < 8; nj++) {
                float pe[4], pel[4];
#pragma unroll
                for (int e = 0; e < 4; e++) {
                    const float p = __expf(s[mi][nj][e] - ((e < 2) ? mn0 : mn1));
                    if (e < 2) la0 += p; else la1 += p;
                    const __nv_bfloat16 hb = __float2bfloat16_rn(p);
                    pe[e]  = p;
                    pel[e] = p - __bfloat162float(hb);
                }
                const int kk = nj >> 1, sel = (nj & 1) * 2;
                ph[mi][kk][sel]     = packbf(pe[0], pe[1]);
                ph[mi][kk][sel + 1] = packbf(pe[2], pe[3]);
                pl[mi][kk][sel]     = packbf(pel[0], pel[1]);
                pl[mi][kk][sel + 1] = packbf(pel[2], pel[3]);
            }
            la0 += __shfl_xor_sync(0xffffffffu, la0, 1);
            la0 += __shfl_xor_sync(0xffffffffu, la0, 2);
            la1 += __shfl_xor_sync(0xffffffffu, la1, 1);
            la1 += __shfl_xor_sync(0xffffffffu, la1, 2);
            l[mi][0] = l[mi][0] * f0 + la0;
            l[mi][1] = l[mi][1] * f1 + la1;
#pragma unroll
            for (int nj = 0; nj < 8; nj++) {
                o[mi][nj][0] *= f0; o[mi][nj][1] *= f0;
                o[mi][nj][2] *= f1; o[mi][nj][3] *= f1;
            }
        }

        // ---- O += phi*vhi + phi*vlo + plo*vhi ----
#pragma unroll
        for (int p = 0; p < 3; p++) {
            const uint32_t vb = (p == 1) ? VL : VH;
#pragma unroll
            for (int kk = 0; kk < 4; kk++)
#pragma unroll
                for (int g = 0; g < 4; g++) {
                    uint32_t bf[4];
                    ldsm4(bf, vb + (g * 16 + brow) * 144 + kk * 32 + bcol2);
#pragma unroll
                    for (int mi = 0; mi < 2; mi++) {
                        const uint32_t* A = (p == 2) ? pl[mi][kk] : ph[mi][kk];
                        mma16816(o[mi][2 * g],     A, bf);
                        mma16816(o[mi][2 * g + 1], A, bf + 2);
                    }
                }
        }

        __syncthreads();
        if (it + 2 < 32) AISSUE(it + 2);
        else CP_COMMIT();
    }
#undef AISSUE

    // ---- epilogue ----
    const int b = bh >> 4, h = bh & 15;
#pragma unroll
    for (int mi = 0; mi < 2; mi++) {
        const float inv0 = 1.0f / l[mi][0], inv1 = 1.0f / l[mi][1];
        const int row0 = q0 + w * 32 + mi * 16 + (lane >> 2);
#pragma unroll
        for (int nj = 0; nj < 8; nj++) {
            const int col = h * 64 + nj * 8 + ((lane & 3) << 1);
            float2 v0 = {o[mi][nj][0] * inv0, o[mi][nj][1] * inv0};
            float2 v1 = {o[mi][nj][2] * inv1, o[mi][nj][3] * inv1};
            *(float2*)(g_ctx + ((size_t)(b * 2048 + row0)) * 1024 + col) = v0;
            *(float2*)(g_ctx + ((size_t)(b * 2048 + row0 + 8)) * 1024 + col) = v1;
        }
    }
}

// ---------------------------------------------------------------------------
extern "C" void kernel_launch(void* const* d_in, const int* in_sizes, int n_in,
                              void* d_out, int out_size)
{
    (void)in_sizes; (void)n_in; (void)out_size;
    const float* q  = (const float*)d_in[0];
    const float* k  = (const float*)d_in[1];
    const float* v  = (const float*)d_in[2];
    const float* Wq = (const float*)d_in[3];
    const float* bq = (const float*)d_in[4];
    const float* Wk = (const float*)d_in[5];
    const float* bk = (const float*)d_in[6];
    const float* Wv = (const float*)d_in[7];
    const float* bv = (const float*)d_in[8];
    const float* Wo = (const float*)d_in[9];
    const float* bo = (const float*)d_in[10];
    float* out = (float*)d_out;

    cudaFuncSetAttribute(attn_tc_kernel, cudaFuncAttributeMaxDynamicSharedMemorySize,
                         ATT_SMEM);

    // Convert weights + activations to split-bf16
    conv_w_kernel<<<dim3(1024, 1, 4), 256>>>(Wq, Wk, Wv, Wo);
    conv_acts_kernel<<<dim3(2048, 1, 3), 256>>>(q, k, v);

    // QKV projections on tensor cores
    qkv_gemm_kernel<<<dim3(8, 32, 3), 256>>>(bq, bk, bv);

    // Attention operand prep + tensor-core flash attention (Q tile 256)
    conv_attn_kernel<<<dim3(32, 32), 256>>>();
    attn_tc_kernel<<<dim3(8, 32), 256, ATT_SMEM>>>();

    // Output projection on tensor cores
    conv_ctx_kernel<<<2048, 256>>>();
    oproj_gemm_kernel<<<dim3(8, 32), 256>>>(bo, out);
}

// round 6
// speedup vs baseline: 1.5902x; 1.0113x over previous
#include <cuda_runtime.h>
#include <cuda_bf16.h>
#include <cstdint>

// Problem constants
constexpr int Bb  = 2;
constexpr int Ss  = 2048;
constexpr int Dd  = 1024;
constexpr int Hh  = 16;
constexpr int HDd = 64;

// ---------------------------------------------------------------------------
// Scratch (allocation-free: __device__ globals)
// ---------------------------------------------------------------------------
__device__ float g_v[Bb * Hh * Ss * HDd];    // [B,H,S,HD] fp32 (for V transpose)

// Split-bf16 GEMM operands (row-major, K contiguous)
__device__ __nv_bfloat16 a_act[4][2 * 4096 * 1024];   // 0..2: q,k,v inputs; 3: ctx
__device__ __nv_bfloat16 b_wt[4][2 * 1024 * 1024];

// Split-bf16 attention operands
__device__ __nv_bfloat16 att_q[2][(size_t)32 * 2048 * 64];   // [bh][s][hd], scale folded
__device__ __nv_bfloat16 att_k[2][(size_t)32 * 2048 * 64];   // [bh][s][hd]
__device__ __nv_bfloat16 att_vt[2][(size_t)32 * 64 * 2048];  // [bh][hd][s]

// ---------------------------------------------------------------------------
// Helpers
// ---------------------------------------------------------------------------
__device__ __forceinline__ uint32_t smem_u32(const void* p) {
    uint32_t a;
    asm("{ .reg .u64 t; cvta.to.shared.u64 t, %1; cvt.u32.u64 %0, t; }"
        : "=r"(a) : "l"(p));
    return a;
}

#define CP16(dst, src) \
    asm volatile("cp.async.cg.shared.global [%0], [%1], 16;" :: "r"(dst), "l"(src))
#define CP_COMMIT() asm volatile("cp.async.commit_group;" ::: "memory")
#define CP_WAIT1()  asm volatile("cp.async.wait_group 1;" ::: "memory")

__device__ __forceinline__ void ldsm4(uint32_t* r, uint32_t addr) {
    asm volatile("ldmatrix.sync.aligned.m8n8.x4.shared.b16 {%0,%1,%2,%3}, [%4];"
        : "=r"(r[0]), "=r"(r[1]), "=r"(r[2]), "=r"(r[3]) : "r"(addr));
}

__device__ __forceinline__ void mma16816(float* c, const uint32_t* a, const uint32_t* b) {
    asm volatile(
        "mma.sync.aligned.m16n8k16.row.col.f32.bf16.bf16.f32 "
        "{%0,%1,%2,%3}, {%4,%5,%6,%7}, {%8,%9}, {%0,%1,%2,%3};"
        : "+f"(c[0]), "+f"(c[1]), "+f"(c[2]), "+f"(c[3])
        : "r"(a[0]), "r"(a[1]), "r"(a[2]), "r"(a[3]), "r"(b[0]), "r"(b[1]));
}

__device__ __forceinline__ uint32_t packbf(float x, float y) {
    __nv_bfloat162 t = __floats2bfloat162_rn(x, y);
    return *(uint32_t*)&t;
}

// Split a float pair into hi/lo bf16 pairs (packed as uint32 each)
__device__ __forceinline__ void split2(float x, float y, uint32_t& hi, uint32_t& lo) {
    hi = packbf(x, y);
    __nv_bfloat162 hb = *(__nv_bfloat162*)&hi;
    lo = packbf(x - __bfloat162float(hb.x), y - __bfloat162float(hb.y));
}

// ---------------------------------------------------------------------------
// Conversion kernels: fp32 -> hi/lo bf16 (GEMM A inputs)
// ---------------------------------------------------------------------------
__device__ __forceinline__ void conv8(const float* __restrict__ src,
                                      __nv_bfloat16* __restrict__ hi,
                                      __nv_bfloat16* __restrict__ lo,
                                      size_t base)
{
    float4 f0 = *(const float4*)(src + base);
    float4 f1 = *(const float4*)(src + base + 4);
    float xs[8] = {f0.x, f0.y, f0.z, f0.w, f1.x, f1.y, f1.z, f1.w};
    union { uint4 u4; __nv_bfloat16 h[8]; } H, L;
#pragma unroll
    for (int j = 0; j < 8; j++) {
        __nv_bfloat16 h = __float2bfloat16_rn(xs[j]);
        H.h[j] = h;
        L.h[j] = __float2bfloat16_rn(xs[j] - __bfloat162float(h));
    }
    *(uint4*)(hi + base) = H.u4;
    *(uint4*)(lo + base) = L.u4;
}

__global__ __launch_bounds__(256)
void conv_acts_kernel(const float* __restrict__ q, const float* __restrict__ k,
                      const float* __restrict__ v)
{
    const int z = blockIdx.z;
    const float* src = (z == 0) ? q : (z == 1) ? k : v;
    const size_t base = ((size_t)blockIdx.x * 256 + threadIdx.x) * 8;
    conv8(src, a_act[z], a_act[z] + (size_t)4096 * 1024, base);
}

__global__ __launch_bounds__(256)
void conv_w_kernel(const float* __restrict__ Wq, const float* __restrict__ Wk,
                   const float* __restrict__ Wv, const float* __restrict__ Wo)
{
    const int w = blockIdx.z;
    const float* W = (w == 0) ? Wq : (w == 1) ? Wk : (w == 2) ? Wv : Wo;
    const int k = blockIdx.x;
    __nv_bfloat16* hi = b_wt[w];
    __nv_bfloat16* lo = b_wt[w] + (size_t)1024 * 1024;
#pragma unroll
    for (int j = 0; j < 4; j++) {
        const int n = threadIdx.x * 4 + j;
        const size_t idx = (w < 3)
            ? ((size_t)(n >> 6) << 16) + (size_t)k * 64 + (n & 63)
            : (size_t)k * 1024 + n;
        const float x = W[idx];
        __nv_bfloat16 h = __float2bfloat16_rn(x);
        hi[(size_t)n * 1024 + k] = h;
        lo[(size_t)n * 1024 + k] = __float2bfloat16_rn(x - __bfloat162float(h));
    }
}

// V-only transpose prep: g_v [bh][s][64] -> att_vt hi/lo [bh][hd][s]
__global__ __launch_bounds__(256)
void conv_attn_v_kernel()
{
    __shared__ float vs[64][65];
    const int bh = blockIdx.y, st = blockIdx.x, t = threadIdx.x;
    const size_t base = ((size_t)bh * 2048 + st * 64) * 64;

    for (int u = t; u < 1024; u += 256) {
        const int s = u >> 4, hd = (u & 15) * 4;
        float4 f = *(const float4*)(g_v + base + (size_t)s * 64 + hd);
        vs[s][hd] = f.x; vs[s][hd + 1] = f.y; vs[s][hd + 2] = f.z; vs[s][hd + 3] = f.w;
    }
    __syncthreads();
    for (int u = t; u < 1024; u += 256) {
        const int hd = u >> 4, s0 = (u & 15) * 4;
        union { uint2 u2; __nv_bfloat16 h[4]; } H, L;
#pragma unroll
        for (int j = 0; j < 4; j++) {
            const float x = vs[s0 + j][hd];
            __nv_bfloat16 h = __float2bfloat16_rn(x);
            H.h[j] = h;
            L.h[j] = __float2bfloat16_rn(x - __bfloat162float(h));
        }
        const size_t o = ((size_t)bh * 64 + hd) * 2048 + st * 64 + s0;
        *(uint2*)(att_vt[0] + o) = H.u2;
        *(uint2*)(att_vt[1] + o) = L.u2;
    }
}

// ---------------------------------------------------------------------------
// mma.sync bf16 GEMM. MODE: 0 = att_q (bias, x0.125, split), 1 = att_k (bias,
// split), 2 = g_v fp32 scatter, 3 = plain fp32 out.
// ---------------------------------------------------------------------------
template<int MODE>
__device__ __forceinline__ void gemm_core(const __nv_bfloat16* __restrict__ At,
                                          const __nv_bfloat16* __restrict__ Bt,
                                          const float* __restrict__ bias,
                                          float* __restrict__ C,
                                          int mt, int nt)
{
    __shared__ __align__(16) __nv_bfloat16 As[2][128][40];
    __shared__ __align__(16) __nv_bfloat16 Bs[2][128][40];

    const int tid = threadIdx.x, lane = tid & 31, wid = tid >> 5;
    const int wm = wid & 1, wn = wid >> 1;

    float acc[4][4][4] = {};

    const int ar  = tid >> 1;
    const int ac0 = (tid & 1) * 2;
    const __nv_bfloat16* Abase = At + (size_t)(mt * 128 + ar) * 1024;
    const __nv_bfloat16* Bbase = Bt + (size_t)(nt * 128 + ar) * 1024;

    const uint32_t sAs = smem_u32(As);
    const uint32_t sBs = smem_u32(Bs);
    const uint32_t dA = sAs + ar * 80 + ac0 * 16;
    const uint32_t dB = sBs + ar * 80 + ac0 * 16;

    const uint32_t a_row = wm * 64 + (lane & 15);
    const uint32_t a_col = (lane >> 4) << 3;
    const uint32_t b_row = wn * 32 + (lane & 7) + ((lane >> 4) << 3);
    const uint32_t b_col = ((lane >> 3) & 1) << 3;

#define ISSUE(kt) do {                                                        \
    const int _kt = (kt);                                                     \
    const int _seg = _kt >> 5, _kk = _kt & 31;                                \
    const int _as = _seg >> 1, _bs = _seg & 1;                                \
    const __nv_bfloat16* _a = Abase + (size_t)_as * 4096 * 1024 + _kk * 32 + ac0 * 8; \
    const __nv_bfloat16* _b = Bbase + (size_t)_bs * 1024 * 1024 + _kk * 32 + ac0 * 8; \
    const uint32_t _da = dA + (_kt & 1) * 10240;                              \
    const uint32_t _db = dB + (_kt & 1) * 10240;                              \
    CP16(_da, _a); CP16(_da + 16, _a + 8);                                    \
    CP16(_db, _b); CP16(_db + 16, _b + 8);                                    \
    CP_COMMIT();                                                              \
} while (0)

    ISSUE(0);
    ISSUE(1);

    for (int kt = 0; kt < 96; kt++) {
        CP_WAIT1();
        __syncthreads();

        const uint32_t sa = sAs + (kt & 1) * 10240;
        const uint32_t sb = sBs + (kt & 1) * 10240;
#pragma unroll
        for (int ks = 0; ks < 32; ks += 16) {
            uint32_t af[4][4], bf[2][4];
#pragma unroll
            for (int mi = 0; mi < 4; mi++)
                ldsm4(af[mi], sa + ((a_row + mi * 16) * 40 + ks + a_col) * 2);
#pragma unroll
            for (int nj2 = 0; nj2 < 2; nj2++)
                ldsm4(bf[nj2], sb + ((b_row + nj2 * 16) * 40 + ks + b_col) * 2);
#pragma unroll
            for (int mi = 0; mi < 4; mi++)
#pragma unroll
                for (int nj = 0; nj < 4; nj++)
                    mma16816(acc[mi][nj], af[mi], &bf[nj >> 1][(nj & 1) * 2]);
        }
        __syncthreads();

        if (kt + 2 < 96) ISSUE(kt + 2);
        else CP_COMMIT();
    }
#undef ISSUE

#pragma unroll
    for (int mi = 0; mi < 4; mi++) {
        const int r0 = mt * 128 + wm * 64 + mi * 16 + (lane >> 2);
#pragma unroll
        for (int nj = 0; nj < 4; nj++) {
            const int col = nt * 128 + wn * 32 + nj * 8 + ((lane & 3) << 1);
            const float b0 = bias[col], b1 = bias[col + 1];
            float c0 = acc[mi][nj][0] + b0, c1 = acc[mi][nj][1] + b1;  // row r0
            float c2 = acc[mi][nj][2] + b0, c3 = acc[mi][nj][3] + b1;  // row r0+8
            if (MODE == 0) { c0 *= 0.125f; c1 *= 0.125f; c2 *= 0.125f; c3 *= 0.125f; }
            if (MODE <= 1) {
                const int h = col >> 6, hd = col & 63;
                __nv_bfloat16* HI = (MODE == 0) ? att_q[0] : att_k[0];
                __nv_bfloat16* LO = (MODE == 0) ? att_q[1] : att_k[1];
                uint32_t hi, lo;
                {
                    const int b_ = r0 >> 11, s = r0 & 2047;
                    const size_t a = ((size_t)((b_ * 16 + h) * 2048 + s)) * 64 + hd;
                    split2(c0, c1, hi, lo);
                    *(uint32_t*)(HI + a) = hi;
                    *(uint32_t*)(LO + a) = lo;
                }
                {
                    const int r1 = r0 + 8;
                    const int b_ = r1 >> 11, s = r1 & 2047;
                    const size_t a = ((size_t)((b_ * 16 + h) * 2048 + s)) * 64 + hd;
                    split2(c2, c3, hi, lo);
                    *(uint32_t*)(HI + a) = hi;
                    *(uint32_t*)(LO + a) = lo;
                }
            } else if (MODE == 2) {
                const int h = col >> 6, hd = col & 63;
                const int b_0 = r0 >> 11, s0 = r0 & 2047;
                const int b_1 = (r0 + 8) >> 11, s1 = (r0 + 8) & 2047;
                *(float2*)(C + ((size_t)((b_0 * 16 + h) * 2048 + s0)) * 64 + hd) = {c0, c1};
                *(float2*)(C + ((size_t)((b_1 * 16 + h) * 2048 + s1)) * 64 + hd) = {c2, c3};
            } else {
                *(float2*)(C + (size_t)r0 * 1024 + col) = {c0, c1};
                *(float2*)(C + (size_t)(r0 + 8) * 1024 + col) = {c2, c3};
            }
        }
    }
}

__global__ __launch_bounds__(256, 2)
void qkv_gemm_kernel(const float* __restrict__ bq, const float* __restrict__ bk,
                     const float* __restrict__ bv)
{
    const int z = blockIdx.z;
    if (z == 0)      gemm_core<0>(a_act[0], b_wt[0], bq, nullptr, blockIdx.y, blockIdx.x);
    else if (z == 1) gemm_core<1>(a_act[1], b_wt[1], bk, nullptr, blockIdx.y, blockIdx.x);
    else             gemm_core<2>(a_act[2], b_wt[2], bv, g_v,     blockIdx.y, blockIdx.x);
}

__global__ __launch_bounds__(256, 2)
void oproj_gemm_kernel(const float* __restrict__ bo, float* __restrict__ out)
{
    gemm_core<3>(a_act[3], b_wt[3], bo, out, blockIdx.y, blockIdx.x);
}

// ---------------------------------------------------------------------------
// Tensor-core flash attention, v3: B-fragment sharing across hi/lo passes.
// Grid (8 q-tiles, 32 bh), 256 threads (8 warps), warp = 32 Q rows.
// Epilogue writes split-bf16 ctx directly into a_act[3].
// ---------------------------------------------------------------------------
constexpr int ATW = 72;
constexpr int ATT_SMEM = 2 * 4 * 64 * ATW * 2;            // 73728 B

__global__ __launch_bounds__(256, 1)
void attn_tc_kernel()
{
    extern __shared__ __nv_bfloat16 smb[];
    const uint32_t sb = smem_u32(smb);
    const int tid = threadIdx.x, lane = tid & 31, w = tid >> 5;
    const int bh = blockIdx.y;
    const int q0 = blockIdx.x * 256;

    // ---- Q fragments ----
    uint32_t qh[2][4][4], ql[2][4][4];
    {
        const int chunk = w >> 2;
        const int wrow  = (w & 3) * 32;
#pragma unroll
        for (int seg = 0; seg < 2; seg++) {
#pragma unroll
            for (int c = 0; c < 2; c++) {
                const __nv_bfloat16* src = att_q[seg] + ((size_t)bh * 2048 + q0 + c * 128) * 64;
                for (int u = tid; u < 1024; u += 256) {
                    const int r = u >> 3, col = (u & 7) * 8;
                    *(uint4*)(smb + r * ATW + col) = *(const uint4*)(src + (size_t)r * 64 + col);
                }
                __syncthreads();
                if (chunk == c) {
#pragma unroll
                    for (int mi = 0; mi < 2; mi++) {
                        const uint32_t ab = sb +
                            (((wrow + mi * 16 + (lane & 15)) * ATW + ((lane >> 4) << 3)) << 1);
#pragma unroll
                        for (int kk = 0; kk < 4; kk++)
                            ldsm4(seg ? ql[mi][kk] : qh[mi][kk], ab + kk * 32);
                    }
                }
                __syncthreads();
            }
        }
    }

    // ---- KV pipeline ----
    const int arr = tid >> 6;
    const int rr0 = tid & 63;
    const __nv_bfloat16* src0;
    size_t step;
    if (arr < 2) { src0 = att_k[arr]      + ((size_t)bh * 2048 + rr0) * 64;  step = 4096; }
    else         { src0 = att_vt[arr - 2] + ((size_t)bh * 64 + rr0) * 2048;  step = 64;   }
    const uint32_t dst0 = sb + arr * 9216 + rr0 * 144;

#define AISSUE(it) do {                                                       \
    const __nv_bfloat16* _s = src0 + (size_t)(it) * step;                     \
    const uint32_t _d = dst0 + ((it) & 1) * 36864;                            \
    CP16(_d,       _s);      CP16(_d + 16,  _s + 8);                          \
    CP16(_d + 32,  _s + 16); CP16(_d + 48,  _s + 24);                         \
    CP16(_d + 64,  _s + 32); CP16(_d + 80,  _s + 40);                         \
    CP16(_d + 96,  _s + 48); CP16(_d + 112, _s + 56);                         \
    CP_COMMIT();                                                              \
} while (0)

    AISSUE(0);
    AISSUE(1);

    const uint32_t brow  = (lane & 7) + ((lane >> 4) << 3);
    const uint32_t bcol2 = (((lane >> 3) & 1) << 3) * 2;

    float o[2][8][4] = {};
    float m[2][2], l[2][2];
#pragma unroll
    for (int mi = 0; mi < 2; mi++) { m[mi][0] = m[mi][1] = -1e30f; l[mi][0] = l[mi][1] = 0.0f; }

    for (int it = 0; it < 32; it++) {
        CP_WAIT1();
        __syncthreads();

        const uint32_t bufb = sb + (it & 1) * 36864;
        const uint32_t KH = bufb, KL = bufb + 9216, VH = bufb + 18432, VL = bufb + 27648;

        // ---- S: KH fragment shared by qh & ql passes; KL pass with qh ----
        float s[2][8][4] = {};
#pragma unroll
        for (int kk = 0; kk < 4; kk++)
#pragma unroll
            for (int g = 0; g < 4; g++) {
                uint32_t bf[4];
                ldsm4(bf, KH + (g * 16 + brow) * 144 + kk * 32 + bcol2);
#pragma unroll
                for (int mi = 0; mi < 2; mi++) {
                    mma16816(s[mi][2 * g],     qh[mi][kk], bf);
                    mma16816(s[mi][2 * g + 1], qh[mi][kk], bf + 2);
                    mma16816(s[mi][2 * g],     ql[mi][kk], bf);
                    mma16816(s[mi][2 * g + 1], ql[mi][kk], bf + 2);
                }
            }
#pragma unroll
        for (int kk = 0; kk < 4; kk++)
#pragma unroll
            for (int g = 0; g < 4; g++) {
                uint32_t bf[4];
                ldsm4(bf, KL + (g * 16 + brow) * 144 + kk * 32 + bcol2);
#pragma unroll
                for (int mi = 0; mi < 2; mi++) {
                    mma16816(s[mi][2 * g],     qh[mi][kk], bf);
                    mma16816(s[mi][2 * g + 1], qh[mi][kk], bf + 2);
                }
            }

        // ---- online softmax + P repack ----
        uint32_t ph[2][4][4], pl[2][4][4];
#pragma unroll
        for (int mi = 0; mi < 2; mi++) {
            float mx0 = -1e30f, mx1 = -1e30f;
#pragma unroll
            for (int nj = 0; nj < 8; nj++) {
                mx0 = fmaxf(mx0, fmaxf(s[mi][nj][0], s[mi][nj][1]));
                mx1 = fmaxf(mx1, fmaxf(s[mi][nj][2], s[mi][nj][3]));
            }
            mx0 = fmaxf(mx0, __shfl_xor_sync(0xffffffffu, mx0, 1));
            mx0 = fmaxf(mx0, __shfl_xor_sync(0xffffffffu, mx0, 2));
            mx1 = fmaxf(mx1, __shfl_xor_sync(0xffffffffu, mx1, 1));
            mx1 = fmaxf(mx1, __shfl_xor_sync(0xffffffffu, mx1, 2));
            const float mn0 = fmaxf(m[mi][0], mx0), mn1 = fmaxf(m[mi][1], mx1);
            const float f0 = __expf(m[mi][0] - mn0), f1 = __expf(m[mi][1] - mn1);
            m[mi][0] = mn0; m[mi][1] = mn1;

            float la0 = 0.0f, la1 = 0.0f;
#pragma unroll
            for (int nj = 0; nj < 8; nj++) {
                float pe[4], pel[4];
#pragma unroll
                for (int e = 0; e < 4; e++) {
                    const float p = __expf(s[mi][nj][e] - ((e < 2) ? mn0 : mn1));
                    if (e < 2) la0 += p; else la1 += p;
                    const __nv_bfloat16 hb = __float2bfloat16_rn(p);
                    pe[e]  = p;
                    pel[e] = p - __bfloat162float(hb);
                }
                const int kk = nj >> 1, sel = (nj & 1) * 2;
                ph[mi][kk][sel]     = packbf(pe[0], pe[1]);
                ph[mi][kk][sel + 1] = packbf(pe[2], pe[3]);
                pl[mi][kk][sel]     = packbf(pel[0], pel[1]);
                pl[mi][kk][sel + 1] = packbf(pel[2], pel[3]);
            }
            la0 += __shfl_xor_sync(0xffffffffu, la0, 1);
            la0 += __shfl_xor_sync(0xffffffffu, la0, 2);
            la1 += __shfl_xor_sync(0xffffffffu, la1, 1);
            la1 += __shfl_xor_sync(0xffffffffu, la1, 2);
            l[mi][0] = l[mi][0] * f0 + la0;
            l[mi][1] = l[mi][1] * f1 + la1;
#pragma unroll
            for (int nj = 0; nj < 8; nj++) {
                o[mi][nj][0] *= f0; o[mi][nj][1] *= f0;
                o[mi][nj][2] *= f1; o[mi][nj][3] *= f1;
            }
        }

        // ---- O: VH fragment shared by ph & pl passes; VL pass with ph ----
#pragma unroll
        for (int kk = 0; kk < 4; kk++)
#pragma unroll
            for (int g = 0; g < 4; g++) {
                uint32_t bf[4];
                ldsm4(bf, VH + (g * 16 + brow) * 144 + kk * 32 + bcol2);
#pragma unroll
                for (int mi = 0; mi < 2; mi++) {
                    mma16816(o[mi][2 * g],     ph[mi][kk], bf);
                    mma16816(o[mi][2 * g + 1], ph[mi][kk], bf + 2);
                    mma16816(o[mi][2 * g],     pl[mi][kk], bf);
                    mma16816(o[mi][2 * g + 1], pl[mi][kk], bf + 2);
                }
            }
#pragma unroll
        for (int kk = 0; kk < 4; kk++)
#pragma unroll
            for (int g = 0; g < 4; g++) {
                uint32_t bf[4];
                ldsm4(bf, VL + (g * 16 + brow) * 144 + kk * 32 + bcol2);
#pragma unroll
                for (int mi = 0; mi < 2; mi++) {
                    mma16816(o[mi][2 * g],     ph[mi][kk], bf);
                    mma16816(o[mi][2 * g + 1], ph[mi][kk], bf + 2);
                }
            }

        __syncthreads();
        if (it + 2 < 32) AISSUE(it + 2);
        else CP_COMMIT();
    }
#undef AISSUE

    // ---- epilogue: write split-bf16 ctx directly into a_act[3] ----
    const int b = bh >> 4, h = bh & 15;
    __nv_bfloat16* HI = a_act[3];
    __nv_bfloat16* LO = a_act[3] + (size_t)4096 * 1024;
#pragma unroll
    for (int mi = 0; mi < 2; mi++) {
        const float inv0 = 1.0f / l[mi][0], inv1 = 1.0f / l[mi][1];
        const int row0 = b * 2048 + q0 + w * 32 + mi * 16 + (lane >> 2);
#pragma unroll
        for (int nj = 0; nj < 8; nj++) {
            const int col = h * 64 + nj * 8 + ((lane & 3) << 1);
            uint32_t hi, lo;
            split2(o[mi][nj][0] * inv0, o[mi][nj][1] * inv0, hi, lo);
            *(uint32_t*)(HI + (size_t)row0 * 1024 + col) = hi;
            *(uint32_t*)(LO + (size_t)row0 * 1024 + col) = lo;
            split2(o[mi][nj][2] * inv1, o[mi][nj][3] * inv1, hi, lo);
            *(uint32_t*)(HI + (size_t)(row0 + 8) * 1024 + col) = hi;
            *(uint32_t*)(LO + (size_t)(row0 + 8) * 1024 + col) = lo;
        }
    }
}

// ---------------------------------------------------------------------------
extern "C" void kernel_launch(void* const* d_in, const int* in_sizes, int n_in,
                              void* d_out, int out_size)
{
    (void)in_sizes; (void)n_in; (void)out_size;
    const float* q  = (const float*)d_in[0];
    const float* k  = (const float*)d_in[1];
    const float* v  = (const float*)d_in[2];
    const float* Wq = (const float*)d_in[3];
    const float* bq = (const float*)d_in[4];
    const float* Wk = (const float*)d_in[5];
    const float* bk = (const float*)d_in[6];
    const float* Wv = (const float*)d_in[7];
    const float* bv = (const float*)d_in[8];
    const float* Wo = (const float*)d_in[9];
    const float* bo = (const float*)d_in[10];
    float* out = (float*)d_out;

    cudaFuncSetAttribute(attn_tc_kernel, cudaFuncAttributeMaxDynamicSharedMemorySize,
                         ATT_SMEM);

    // Convert weights + activations to split-bf16 (GEMM inputs)
    conv_w_kernel<<<dim3(1024, 1, 4), 256>>>(Wq, Wk, Wv, Wo);
    conv_acts_kernel<<<dim3(2048, 1, 3), 256>>>(q, k, v);

    // QKV projections; epilogues emit att_q/att_k split-bf16 and g_v fp32
    qkv_gemm_kernel<<<dim3(8, 32, 3), 256>>>(bq, bk, bv);

    // V transpose prep + tensor-core flash attention (writes a_act[3] split)
    conv_attn_v_kernel<<<dim3(32, 32), 256>>>();
    attn_tc_kernel<<<dim3(8, 32), 256, ATT_SMEM>>>();

    // Output projection
    oproj_gemm_kernel<<<dim3(8, 32), 256>>>(bo, out);
}

// round 7
// speedup vs baseline: 1.5997x; 1.0060x over previous
#include <cuda_runtime.h>
#include <cuda_bf16.h>
#include <cstdint>

// Problem constants
constexpr int Bb  = 2;
constexpr int Ss  = 2048;
constexpr int Dd  = 1024;
constexpr int Hh  = 16;
constexpr int HDd = 64;

// ---------------------------------------------------------------------------
// Scratch (allocation-free: __device__ globals)
// ---------------------------------------------------------------------------
__device__ float g_v[Bb * Hh * Ss * HDd];    // [B,H,S,HD] fp32 (for V transpose)

// Split-bf16 GEMM operands (row-major, K contiguous)
__device__ __nv_bfloat16 a_act[4][2 * 4096 * 1024];   // 0..2: q,k,v inputs; 3: ctx
__device__ __nv_bfloat16 b_wt[4][2 * 1024 * 1024];

// Split-bf16 attention operands
__device__ __nv_bfloat16 att_q[2][(size_t)32 * 2048 * 64];   // [bh][s][hd], scale folded
__device__ __nv_bfloat16 att_k[2][(size_t)32 * 2048 * 64];   // [bh][s][hd]
__device__ __nv_bfloat16 att_vt[2][(size_t)32 * 64 * 2048];  // [bh][hd][s]

// ---------------------------------------------------------------------------
// Helpers
// ---------------------------------------------------------------------------
__device__ __forceinline__ uint32_t smem_u32(const void* p) {
    uint32_t a;
    asm("{ .reg .u64 t; cvta.to.shared.u64 t, %1; cvt.u32.u64 %0, t; }"
        : "=r"(a) : "l"(p));
    return a;
}

#define CP16(dst, src) \
    asm volatile("cp.async.cg.shared.global [%0], [%1], 16;" :: "r"(dst), "l"(src))
#define CP_COMMIT() asm volatile("cp.async.commit_group;" ::: "memory")
#define CP_WAIT1()  asm volatile("cp.async.wait_group 1;" ::: "memory")

__device__ __forceinline__ void ldsm4(uint32_t* r, uint32_t addr) {
    asm volatile("ldmatrix.sync.aligned.m8n8.x4.shared.b16 {%0,%1,%2,%3}, [%4];"
        : "=r"(r[0]), "=r"(r[1]), "=r"(r[2]), "=r"(r[3]) : "r"(addr));
}

__device__ __forceinline__ void mma16816(float* c, const uint32_t* a, const uint32_t* b) {
    asm volatile(
        "mma.sync.aligned.m16n8k16.row.col.f32.bf16.bf16.f32 "
        "{%0,%1,%2,%3}, {%4,%5,%6,%7}, {%8,%9}, {%0,%1,%2,%3};"
        : "+f"(c[0]), "+f"(c[1]), "+f"(c[2]), "+f"(c[3])
        : "r"(a[0]), "r"(a[1]), "r"(a[2]), "r"(a[3]), "r"(b[0]), "r"(b[1]));
}

__device__ __forceinline__ uint32_t packbf(float x, float y) {
    __nv_bfloat162 t = __floats2bfloat162_rn(x, y);
    return *(uint32_t*)&t;
}

__device__ __forceinline__ void split2(float x, float y, uint32_t& hi, uint32_t& lo) {
    hi = packbf(x, y);
    __nv_bfloat162 hb = *(__nv_bfloat162*)&hi;
    lo = packbf(x - __bfloat162float(hb.x), y - __bfloat162float(hb.y));
}

// ---------------------------------------------------------------------------
// Conversion kernels: fp32 -> hi/lo bf16 (GEMM A inputs)
// ---------------------------------------------------------------------------
__device__ __forceinline__ void conv8(const float* __restrict__ src,
                                      __nv_bfloat16* __restrict__ hi,
                                      __nv_bfloat16* __restrict__ lo,
                                      size_t base)
{
    float4 f0 = *(const float4*)(src + base);
    float4 f1 = *(const float4*)(src + base + 4);
    float xs[8] = {f0.x, f0.y, f0.z, f0.w, f1.x, f1.y, f1.z, f1.w};
    union { uint4 u4; __nv_bfloat16 h[8]; } H, L;
#pragma unroll
    for (int j = 0; j < 8; j++) {
        __nv_bfloat16 h = __float2bfloat16_rn(xs[j]);
        H.h[j] = h;
        L.h[j] = __float2bfloat16_rn(xs[j] - __bfloat162float(h));
    }
    *(uint4*)(hi + base) = H.u4;
    *(uint4*)(lo + base) = L.u4;
}

__global__ __launch_bounds__(256)
void conv_acts_kernel(const float* __restrict__ q, const float* __restrict__ k,
                      const float* __restrict__ v)
{
    const int z = blockIdx.z;
    const float* src = (z == 0) ? q : (z == 1) ? k : v;
    const size_t base = ((size_t)blockIdx.x * 256 + threadIdx.x) * 8;
    conv8(src, a_act[z], a_act[z] + (size_t)4096 * 1024, base);
}

__global__ __launch_bounds__(256)
void conv_w_kernel(const float* __restrict__ Wq, const float* __restrict__ Wk,
                   const float* __restrict__ Wv, const float* __restrict__ Wo)
{
    const int w = blockIdx.z;
    const float* W = (w == 0) ? Wq : (w == 1) ? Wk : (w == 2) ? Wv : Wo;
    const int k = blockIdx.x;
    __nv_bfloat16* hi = b_wt[w];
    __nv_bfloat16* lo = b_wt[w] + (size_t)1024 * 1024;
#pragma unroll
    for (int j = 0; j < 4; j++) {
        const int n = threadIdx.x * 4 + j;
        const size_t idx = (w < 3)
            ? ((size_t)(n >> 6) << 16) + (size_t)k * 64 + (n & 63)
            : (size_t)k * 1024 + n;
        const float x = W[idx];
        __nv_bfloat16 h = __float2bfloat16_rn(x);
        hi[(size_t)n * 1024 + k] = h;
        lo[(size_t)n * 1024 + k] = __float2bfloat16_rn(x - __bfloat162float(h));
    }
}

// V-only transpose prep: g_v [bh][s][64] -> att_vt hi/lo [bh][hd][s]
__global__ __launch_bounds__(256)
void conv_attn_v_kernel()
{
    __shared__ float vs[64][65];
    const int bh = blockIdx.y, st = blockIdx.x, t = threadIdx.x;
    const size_t base = ((size_t)bh * 2048 + st * 64) * 64;

    for (int u = t; u < 1024; u += 256) {
        const int s = u >> 4, hd = (u & 15) * 4;
        float4 f = *(const float4*)(g_v + base + (size_t)s * 64 + hd);
        vs[s][hd] = f.x; vs[s][hd + 1] = f.y; vs[s][hd + 2] = f.z; vs[s][hd + 3] = f.w;
    }
    __syncthreads();
    for (int u = t; u < 1024; u += 256) {
        const int hd = u >> 4, s0 = (u & 15) * 4;
        union { uint2 u2; __nv_bfloat16 h[4]; } H, L;
#pragma unroll
        for (int j = 0; j < 4; j++) {
            const float x = vs[s0 + j][hd];
            __nv_bfloat16 h = __float2bfloat16_rn(x);
            H.h[j] = h;
            L.h[j] = __float2bfloat16_rn(x - __bfloat162float(h));
        }
        const size_t o = ((size_t)bh * 64 + hd) * 2048 + st * 64 + s0;
        *(uint2*)(att_vt[0] + o) = H.u2;
        *(uint2*)(att_vt[1] + o) = L.u2;
    }
}

// ---------------------------------------------------------------------------
// mma.sync bf16 GEMM. MODE: 0 = att_q (bias, x0.125, split), 1 = att_k (bias,
// split), 2 = g_v fp32 scatter, 3 = plain fp32 out.
// ---------------------------------------------------------------------------
template<int MODE>
__device__ __forceinline__ void gemm_core(const __nv_bfloat16* __restrict__ At,
                                          const __nv_bfloat16* __restrict__ Bt,
                                          const float* __restrict__ bias,
                                          float* __restrict__ C,
                                          int mt, int nt)
{
    __shared__ __align__(16) __nv_bfloat16 As[2][128][40];
    __shared__ __align__(16) __nv_bfloat16 Bs[2][128][40];

    const int tid = threadIdx.x, lane = tid & 31, wid = tid >> 5;
    const int wm = wid & 1, wn = wid >> 1;

    float acc[4][4][4] = {};

    const int ar  = tid >> 1;
    const int ac0 = (tid & 1) * 2;
    const __nv_bfloat16* Abase = At + (size_t)(mt * 128 + ar) * 1024;
    const __nv_bfloat16* Bbase = Bt + (size_t)(nt * 128 + ar) * 1024;

    const uint32_t sAs = smem_u32(As);
    const uint32_t sBs = smem_u32(Bs);
    const uint32_t dA = sAs + ar * 80 + ac0 * 16;
    const uint32_t dB = sBs + ar * 80 + ac0 * 16;

    const uint32_t a_row = wm * 64 + (lane & 15);
    const uint32_t a_col = (lane >> 4) << 3;
    const uint32_t b_row = wn * 32 + (lane & 7) + ((lane >> 4) << 3);
    const uint32_t b_col = ((lane >> 3) & 1) << 3;

#define ISSUE(kt) do {                                                        \
    const int _kt = (kt);                                                     \
    const int _seg = _kt >> 5, _kk = _kt & 31;                                \
    const int _as = _seg >> 1, _bs = _seg & 1;                                \
    const __nv_bfloat16* _a = Abase + (size_t)_as * 4096 * 1024 + _kk * 32 + ac0 * 8; \
    const __nv_bfloat16* _b = Bbase + (size_t)_bs * 1024 * 1024 + _kk * 32 + ac0 * 8; \
    const uint32_t _da = dA + (_kt & 1) * 10240;                              \
    const uint32_t _db = dB + (_kt & 1) * 10240;                              \
    CP16(_da, _a); CP16(_da + 16, _a + 8);                                    \
    CP16(_db, _b); CP16(_db + 16, _b + 8);                                    \
    CP_COMMIT();                                                              \
} while (0)

    ISSUE(0);
    ISSUE(1);

    for (int kt = 0; kt < 96; kt++) {
        CP_WAIT1();
        __syncthreads();

        const uint32_t sa = sAs + (kt & 1) * 10240;
        const uint32_t sb = sBs + (kt & 1) * 10240;
#pragma unroll
        for (int ks = 0; ks < 32; ks += 16) {
            uint32_t af[4][4], bf[2][4];
#pragma unroll
            for (int mi = 0; mi < 4; mi++)
                ldsm4(af[mi], sa + ((a_row + mi * 16) * 40 + ks + a_col) * 2);
#pragma unroll
            for (int nj2 = 0; nj2 < 2; nj2++)
                ldsm4(bf[nj2], sb + ((b_row + nj2 * 16) * 40 + ks + b_col) * 2);
#pragma unroll
            for (int mi = 0; mi < 4; mi++)
#pragma unroll
                for (int nj = 0; nj < 4; nj++)
                    mma16816(acc[mi][nj], af[mi], &bf[nj >> 1][(nj & 1) * 2]);
        }
        __syncthreads();

        if (kt + 2 < 96) ISSUE(kt + 2);
        else CP_COMMIT();
    }
#undef ISSUE

#pragma unroll
    for (int mi = 0; mi < 4; mi++) {
        const int r0 = mt * 128 + wm * 64 + mi * 16 + (lane >> 2);
#pragma unroll
        for (int nj = 0; nj < 4; nj++) {
            const int col = nt * 128 + wn * 32 + nj * 8 + ((lane & 3) << 1);
            const float b0 = bias[col], b1 = bias[col + 1];
            float c0 = acc[mi][nj][0] + b0, c1 = acc[mi][nj][1] + b1;
            float c2 = acc[mi][nj][2] + b0, c3 = acc[mi][nj][3] + b1;
            if (MODE == 0) { c0 *= 0.125f; c1 *= 0.125f; c2 *= 0.125f; c3 *= 0.125f; }
            if (MODE <= 1) {
                const int h = col >> 6, hd = col & 63;
                __nv_bfloat16* HI = (MODE == 0) ? att_q[0] : att_k[0];
                __nv_bfloat16* LO = (MODE == 0) ? att_q[1] : att_k[1];
                uint32_t hi, lo;
                {
                    const int b_ = r0 >> 11, s = r0 & 2047;
                    const size_t a = ((size_t)((b_ * 16 + h) * 2048 + s)) * 64 + hd;
                    split2(c0, c1, hi, lo);
                    *(uint32_t*)(HI + a) = hi;
                    *(uint32_t*)(LO + a) = lo;
                }
                {
                    const int r1 = r0 + 8;
                    const int b_ = r1 >> 11, s = r1 & 2047;
                    const size_t a = ((size_t)((b_ * 16 + h) * 2048 + s)) * 64 + hd;
                    split2(c2, c3, hi, lo);
                    *(uint32_t*)(HI + a) = hi;
                    *(uint32_t*)(LO + a) = lo;
                }
            } else if (MODE == 2) {
                const int h = col >> 6, hd = col & 63;
                const int b_0 = r0 >> 11, s0 = r0 & 2047;
                const int b_1 = (r0 + 8) >> 11, s1 = (r0 + 8) & 2047;
                *(float2*)(C + ((size_t)((b_0 * 16 + h) * 2048 + s0)) * 64 + hd) = {c0, c1};
                *(float2*)(C + ((size_t)((b_1 * 16 + h) * 2048 + s1)) * 64 + hd) = {c2, c3};
            } else {
                *(float2*)(C + (size_t)r0 * 1024 + col) = {c0, c1};
                *(float2*)(C + (size_t)(r0 + 8) * 1024 + col) = {c2, c3};
            }
        }
    }
}

__global__ __launch_bounds__(256, 2)
void qkv_gemm_kernel(const float* __restrict__ bq, const float* __restrict__ bk,
                     const float* __restrict__ bv)
{
    const int z = blockIdx.z;
    if (z == 0)      gemm_core<0>(a_act[0], b_wt[0], bq, nullptr, blockIdx.y, blockIdx.x);
    else if (z == 1) gemm_core<1>(a_act[1], b_wt[1], bk, nullptr, blockIdx.y, blockIdx.x);
    else             gemm_core<2>(a_act[2], b_wt[2], bv, g_v,     blockIdx.y, blockIdx.x);
}

__global__ __launch_bounds__(256, 2)
void oproj_gemm_kernel(const float* __restrict__ bo, float* __restrict__ out)
{
    gemm_core<3>(a_act[3], b_wt[3], bo, out, blockIdx.y, blockIdx.x);
}

// ---------------------------------------------------------------------------
// Tensor-core flash attention, v4: register-level B-fragment software
// pipelining (ldsm for step i+1 issued before MMAs of step i).
// Grid (8 q-tiles, 32 bh), 256 threads (8 warps), warp = 32 Q rows.
// ---------------------------------------------------------------------------
constexpr int ATW = 72;
constexpr int ATT_SMEM = 2 * 4 * 64 * ATW * 2;            // 73728 B

__global__ __launch_bounds__(256, 1)
void attn_tc_kernel()
{
    extern __shared__ __nv_bfloat16 smb[];
    const uint32_t sb = smem_u32(smb);
    const int tid = threadIdx.x, lane = tid & 31, w = tid >> 5;
    const int bh = blockIdx.y;
    const int q0 = blockIdx.x * 256;

    // ---- Q fragments ----
    uint32_t qh[2][4][4], ql[2][4][4];
    {
        const int chunk = w >> 2;
        const int wrow  = (w & 3) * 32;
#pragma unroll
        for (int seg = 0; seg < 2; seg++) {
#pragma unroll
            for (int c = 0; c < 2; c++) {
                const __nv_bfloat16* src = att_q[seg] + ((size_t)bh * 2048 + q0 + c * 128) * 64;
                for (int u = tid; u < 1024; u += 256) {
                    const int r = u >> 3, col = (u & 7) * 8;
                    *(uint4*)(smb + r * ATW + col) = *(const uint4*)(src + (size_t)r * 64 + col);
                }
                __syncthreads();
                if (chunk == c) {
#pragma unroll
                    for (int mi = 0; mi < 2; mi++) {
                        const uint32_t ab = sb +
                            (((wrow + mi * 16 + (lane & 15)) * ATW + ((lane >> 4) << 3)) << 1);
#pragma unroll
                        for (int kk = 0; kk < 4; kk++)
                            ldsm4(seg ? ql[mi][kk] : qh[mi][kk], ab + kk * 32);
                    }
                }
                __syncthreads();
            }
        }
    }

    // ---- KV pipeline ----
    const int arr = tid >> 6;
    const int rr0 = tid & 63;
    const __nv_bfloat16* src0;
    size_t step;
    if (arr < 2) { src0 = att_k[arr]      + ((size_t)bh * 2048 + rr0) * 64;  step = 4096; }
    else         { src0 = att_vt[arr - 2] + ((size_t)bh * 64 + rr0) * 2048;  step = 64;   }
    const uint32_t dst0 = sb + arr * 9216 + rr0 * 144;

#define AISSUE(it) do {                                                       \
    const __nv_bfloat16* _s = src0 + (size_t)(it) * step;                     \
    const uint32_t _d = dst0 + ((it) & 1) * 36864;                            \
    CP16(_d,       _s);      CP16(_d + 16,  _s + 8);                          \
    CP16(_d + 32,  _s + 16); CP16(_d + 48,  _s + 24);                         \
    CP16(_d + 64,  _s + 32); CP16(_d + 80,  _s + 40);                         \
    CP16(_d + 96,  _s + 48); CP16(_d + 112, _s + 56);                         \
    CP_COMMIT();                                                              \
} while (0)

    AISSUE(0);
    AISSUE(1);

    const uint32_t brow  = (lane & 7) + ((lane >> 4) << 3);
    const uint32_t bcol2 = (((lane >> 3) & 1) << 3) * 2;
    const uint32_t boff  = brow * 144 + bcol2;

    float o[2][8][4] = {};
    float m[2][2], l[2][2];
#pragma unroll
    for (int mi = 0; mi < 2; mi++) { m[mi][0] = m[mi][1] = -1e30f; l[mi][0] = l[mi][1] = 0.0f; }

    for (int it = 0; it < 32; it++) {
        CP_WAIT1();
        __syncthreads();

        const uint32_t bufb = sb + (it & 1) * 36864;
        const uint32_t KH = bufb, KL = bufb + 9216, VH = bufb + 18432, VL = bufb + 27648;

        // ---- S: 32-step pipelined stream (steps 0-15: KH, 16-31: KL) ----
        float s[2][8][4] = {};
        {
            uint32_t bfb[2][4];
            ldsm4(bfb[0], KH + boff);
#pragma unroll
            for (int i = 0; i < 32; i++) {
                if (i + 1 < 32) {
                    const int j = i + 1, jk = (j & 15) >> 2, jg = j & 3;
                    const uint32_t base = (j < 16) ? KH : KL;
                    ldsm4(bfb[j & 1], base + (jg * 16) * 144 + jk * 32 + boff);
                }
                const uint32_t* bf = bfb[i & 1];
                const int kk = (i & 15) >> 2, g = i & 3;
#pragma unroll
                for (int mi = 0; mi < 2; mi++) {
                    mma16816(s[mi][2 * g],     qh[mi][kk], bf);
                    mma16816(s[mi][2 * g + 1], qh[mi][kk], bf + 2);
                    if (i < 16) {
                        mma16816(s[mi][2 * g],     ql[mi][kk], bf);
                        mma16816(s[mi][2 * g + 1], ql[mi][kk], bf + 2);
                    }
                }
            }
        }

        // Prefetch first V fragment; its latency hides behind the softmax.
        uint32_t bfv[2][4];
        ldsm4(bfv[0], VH + boff);

        // ---- online softmax + P repack ----
        uint32_t ph[2][4][4], pl[2][4][4];
#pragma unroll
        for (int mi = 0; mi < 2; mi++) {
            float mx0 = -1e30f, mx1 = -1e30f;
#pragma unroll
            for (int nj = 0; nj < 8; nj++) {
                mx0 = fmaxf(mx0, fmaxf(s[mi][nj][0], s[mi][nj][1]));
                mx1 = fmaxf(mx1, fmaxf(s[mi][nj][2], s[mi][nj][3]));
            }
            mx0 = fmaxf(mx0, __shfl_xor_sync(0xffffffffu, mx0, 1));
            mx0 = fmaxf(mx0, __shfl_xor_sync(0xffffffffu, mx0, 2));
            mx1 = fmaxf(mx1, __shfl_xor_sync(0xffffffffu, mx1, 1));
            mx1 = fmaxf(mx1, __shfl_xor_sync(0xffffffffu, mx1, 2));
            const float mn0 = fmaxf(m[mi][0], mx0), mn1 = fmaxf(m[mi][1], mx1);
            const float f0 = __expf(m[mi][0] - mn0), f1 = __expf(m[mi][1] - mn1);
            m[mi][0] = mn0; m[mi][1] = mn1;

            float la0 = 0.0f, la1 = 0.0f;
#pragma unroll
            for (int nj = 0; nj < 8; nj++) {
                float pe[4], pel[4];
#pragma unroll
                for (int e = 0; e < 4; e++) {
                    const float p = __expf(s[mi][nj][e] - ((e < 2) ? mn0 : mn1));
                    if (e < 2) la0 += p; else la1 += p;
                    const __nv_bfloat16 hb = __float2bfloat16_rn(p);
                    pe[e]  = p;
                    pel[e] = p - __bfloat162float(hb);
                }
                const int kk = nj >> 1, sel = (nj & 1) * 2;
                ph[mi][kk][sel]     = packbf(pe[0], pe[1]);
                ph[mi][kk][sel + 1] = packbf(pe[2], pe[3]);
                pl[mi][kk][sel]     = packbf(pel[0], pel[1]);
                pl[mi][kk][sel + 1] = packbf(pel[2], pel[3]);
            }
            la0 += __shfl_xor_sync(0xffffffffu, la0, 1);
            la0 += __shfl_xor_sync(0xffffffffu, la0, 2);
            la1 += __shfl_xor_sync(0xffffffffu, la1, 1);
            la1 += __shfl_xor_sync(0xffffffffu, la1, 2);
            l[mi][0] = l[mi][0] * f0 + la0;
            l[mi][1] = l[mi][1] * f1 + la1;
#pragma unroll
            for (int nj = 0; nj < 8; nj++) {
                o[mi][nj][0] *= f0; o[mi][nj][1] *= f0;
                o[mi][nj][2] *= f1; o[mi][nj][3] *= f1;
            }
        }

        // ---- O: 32-step pipelined stream (steps 0-15: VH, 16-31: VL) ----
#pragma unroll
        for (int i = 0; i < 32; i++) {
            if (i + 1 < 32) {
                const int j = i + 1, jk = (j & 15) >> 2, jg = j & 3;
                const uint32_t base = (j < 16) ? VH : VL;
                ldsm4(bfv[j & 1], base + (jg * 16) * 144 + jk * 32 + boff);
            }
            const uint32_t* bf = bfv[i & 1];
            const int kk = (i & 15) >> 2, g = i & 3;
#pragma unroll
            for (int mi = 0; mi < 2; mi++) {
                mma16816(o[mi][2 * g],     ph[mi][kk], bf);
                mma16816(o[mi][2 * g + 1], ph[mi][kk], bf + 2);
                if (i < 16) {
                    mma16816(o[mi][2 * g],     pl[mi][kk], bf);
                    mma16816(o[mi][2 * g + 1], pl[mi][kk], bf + 2);
                }
            }
        }

        __syncthreads();
        if (it + 2 < 32) AISSUE(it + 2);
        else CP_COMMIT();
    }
#undef AISSUE

    // ---- epilogue: write split-bf16 ctx directly into a_act[3] ----
    const int b = bh >> 4, h = bh & 15;
    __nv_bfloat16* HI = a_act[3];
    __nv_bfloat16* LO = a_act[3] + (size_t)4096 * 1024;
#pragma unroll
    for (int mi = 0; mi < 2; mi++) {
        const float inv0 = 1.0f / l[mi][0], inv1 = 1.0f / l[mi][1];
        const int row0 = b * 2048 + q0 + w * 32 + mi * 16 + (lane >> 2);
#pragma unroll
        for (int nj = 0; nj < 8; nj++) {
            const int col = h * 64 + nj * 8 + ((lane & 3) << 1);
            uint32_t hi, lo;
            split2(o[mi][nj][0] * inv0, o[mi][nj][1] * inv0, hi, lo);
            *(uint32_t*)(HI + (size_t)row0 * 1024 + col) = hi;
            *(uint32_t*)(LO + (size_t)row0 * 1024 + col) = lo;
            split2(o[mi][nj][2] * inv1, o[mi][nj][3] * inv1, hi, lo);
            *(uint32_t*)(HI + (size_t)(row0 + 8) * 1024 + col) = hi;
            *(uint32_t*)(LO + (size_t)(row0 + 8) * 1024 + col) = lo;
        }
    }
}

// ---------------------------------------------------------------------------
extern "C" void kernel_launch(void* const* d_in, const int* in_sizes, int n_in,
                              void* d_out, int out_size)
{
    (void)in_sizes; (void)n_in; (void)out_size;
    const float* q  = (const float*)d_in[0];
    const float* k  = (const float*)d_in[1];
    const float* v  = (const float*)d_in[2];
    const float* Wq = (const float*)d_in[3];
    const float* bq = (const float*)d_in[4];
    const float* Wk = (const float*)d_in[5];
    const float* bk = (const float*)d_in[6];
    const float* Wv = (const float*)d_in[7];
    const float* bv = (const float*)d_in[8];
    const float* Wo = (const float*)d_in[9];
    const float* bo = (const float*)d_in[10];
    float* out = (float*)d_out;

    cudaFuncSetAttribute(attn_tc_kernel, cudaFuncAttributeMaxDynamicSharedMemorySize,
                         ATT_SMEM);

    conv_w_kernel<<<dim3(1024, 1, 4), 256>>>(Wq, Wk, Wv, Wo);
    conv_acts_kernel<<<dim3(2048, 1, 3), 256>>>(q, k, v);

    qkv_gemm_kernel<<<dim3(8, 32, 3), 256>>>(bq, bk, bv);

    conv_attn_v_kernel<<<dim3(32, 32), 256>>>();
    attn_tc_kernel<<<dim3(8, 32), 256, ATT_SMEM>>>();

    oproj_gemm_kernel<<<dim3(8, 32), 256>>>(bo, out);
}

// round 8
// speedup vs baseline: 2.3598x; 1.4751x over previous
#include <cuda_runtime.h>
#include <cuda_fp16.h>
#include <cstdint>

// Problem constants
constexpr int Bb  = 2;
constexpr int Ss  = 2048;
constexpr int Dd  = 1024;
constexpr int Hh  = 16;
constexpr int HDd = 64;

// ---------------------------------------------------------------------------
// Scratch (allocation-free: __device__ globals)
// ---------------------------------------------------------------------------
__device__ float g_v[Bb * Hh * Ss * HDd];    // [B,H,S,HD] fp32 (for V transpose)

// Split-fp16 GEMM operands (row-major, K contiguous). A: hi+lo segs; B: hi only.
__device__ __half a_act[4][2 * 4096 * 1024];   // 0..2: q,k,v inputs; 3: ctx
__device__ __half b_wt[4][1024 * 1024];

// fp16 attention operands
__device__ __half att_q[2][(size_t)32 * 2048 * 64];   // [bh][s][hd] hi/lo, UNscaled
__device__ __half att_k[(size_t)32 * 2048 * 64];      // [bh][s][hd] hi, x0.125 folded
__device__ __half att_vt[(size_t)32 * 64 * 2048];     // [bh][hd][s] hi

// ---------------------------------------------------------------------------
// Helpers
// ---------------------------------------------------------------------------
__device__ __forceinline__ uint32_t smem_u32(const void* p) {
    uint32_t a;
    asm("{ .reg .u64 t; cvta.to.shared.u64 t, %1; cvt.u32.u64 %0, t; }"
        : "=r"(a) : "l"(p));
    return a;
}

#define CP16(dst, src) \
    asm volatile("cp.async.cg.shared.global [%0], [%1], 16;" :: "r"(dst), "l"(src))
#define CP_COMMIT() asm volatile("cp.async.commit_group;" ::: "memory")
#define CP_WAIT1()  asm volatile("cp.async.wait_group 1;" ::: "memory")

__device__ __forceinline__ void ldsm4(uint32_t* r, uint32_t addr) {
    asm volatile("ldmatrix.sync.aligned.m8n8.x4.shared.b16 {%0,%1,%2,%3}, [%4];"
        : "=r"(r[0]), "=r"(r[1]), "=r"(r[2]), "=r"(r[3]) : "r"(addr));
}

__device__ __forceinline__ void mma16816(float* c, const uint32_t* a, const uint32_t* b) {
    asm volatile(
        "mma.sync.aligned.m16n8k16.row.col.f32.f16.f16.f32 "
        "{%0,%1,%2,%3}, {%4,%5,%6,%7}, {%8,%9}, {%0,%1,%2,%3};"
        : "+f"(c[0]), "+f"(c[1]), "+f"(c[2]), "+f"(c[3])
        : "r"(a[0]), "r"(a[1]), "r"(a[2]), "r"(a[3]), "r"(b[0]), "r"(b[1]));
}

__device__ __forceinline__ uint32_t packh(float x, float y) {
    __half2 t = __floats2half2_rn(x, y);
    return *(uint32_t*)&t;
}

__device__ __forceinline__ void split2h(float x, float y, uint32_t& hi, uint32_t& lo) {
    hi = packh(x, y);
    __half2 hb = *(__half2*)&hi;
    lo = packh(x - __half2float(hb.x), y - __half2float(hb.y));
}

// ---------------------------------------------------------------------------
// Conversion kernels: fp32 -> hi/lo fp16 (GEMM A inputs)
// ---------------------------------------------------------------------------
__device__ __forceinline__ void conv8h(const float* __restrict__ src,
                                       __half* __restrict__ hi,
                                       __half* __restrict__ lo,
                                       size_t base)
{
    float4 f0 = *(const float4*)(src + base);
    float4 f1 = *(const float4*)(src + base + 4);
    float xs[8] = {f0.x, f0.y, f0.z, f0.w, f1.x, f1.y, f1.z, f1.w};
    union { uint4 u4; __half h[8]; } H, L;
#pragma unroll
    for (int j = 0; j < 8; j++) {
        __half h = __float2half_rn(xs[j]);
        H.h[j] = h;
        L.h[j] = __float2half_rn(xs[j] - __half2float(h));
    }
    *(uint4*)(hi + base) = H.u4;
    *(uint4*)(lo + base) = L.u4;
}

__global__ __launch_bounds__(256)
void conv_acts_kernel(const float* __restrict__ q, const float* __restrict__ k,
                      const float* __restrict__ v)
{
    const int z = blockIdx.z;
    const float* src = (z == 0) ? q : (z == 1) ? k : v;
    const size_t base = ((size_t)blockIdx.x * 256 + threadIdx.x) * 8;
    conv8h(src, a_act[z], a_act[z] + (size_t)4096 * 1024, base);
}

// Weights -> B^T [n][k], hi only.
__global__ __launch_bounds__(256)
void conv_w_kernel(const float* __restrict__ Wq, const float* __restrict__ Wk,
                   const float* __restrict__ Wv, const float* __restrict__ Wo)
{
    const int w = blockIdx.z;
    const float* W = (w == 0) ? Wq : (w == 1) ? Wk : (w == 2) ? Wv : Wo;
    const int k = blockIdx.x;
    __half* hi = b_wt[w];
#pragma unroll
    for (int j = 0; j < 4; j++) {
        const int n = threadIdx.x * 4 + j;
        const size_t idx = (w < 3)
            ? ((size_t)(n >> 6) << 16) + (size_t)k * 64 + (n & 63)
            : (size_t)k * 1024 + n;
        hi[(size_t)n * 1024 + k] = __float2half_rn(W[idx]);
    }
}

// V-only transpose prep: g_v [bh][s][64] -> att_vt hi [bh][hd][s]
__global__ __launch_bounds__(256)
void conv_attn_v_kernel()
{
    __shared__ float vs[64][65];
    const int bh = blockIdx.y, st = blockIdx.x, t = threadIdx.x;
    const size_t base = ((size_t)bh * 2048 + st * 64) * 64;

    for (int u = t; u < 1024; u += 256) {
        const int s = u >> 4, hd = (u & 15) * 4;
        float4 f = *(const float4*)(g_v + base + (size_t)s * 64 + hd);
        vs[s][hd] = f.x; vs[s][hd + 1] = f.y; vs[s][hd + 2] = f.z; vs[s][hd + 3] = f.w;
    }
    __syncthreads();
    for (int u = t; u < 1024; u += 256) {
        const int hd = u >> 4, s0 = (u & 15) * 4;
        union { uint2 u2; __half h[4]; } H;
#pragma unroll
        for (int j = 0; j < 4; j++)
            H.h[j] = __float2half_rn(vs[s0 + j][hd]);
        const size_t o = ((size_t)bh * 64 + hd) * 2048 + st * 64 + s0;
        *(uint2*)(att_vt + o) = H.u2;
    }
}

// ---------------------------------------------------------------------------
// mma.sync fp16 GEMM, 2-pass split (A hi/lo, B hi). K_eff = 2048 (64 kt).
// MODE: 0 = att_q (bias, hi/lo split), 1 = att_k (bias, x0.125, hi),
//       2 = g_v fp32 scatter, 3 = plain fp32 out.
// ---------------------------------------------------------------------------
template<int MODE>
__device__ __forceinline__ void gemm_core(const __half* __restrict__ At,
                                          const __half* __restrict__ Bt,
                                          const float* __restrict__ bias,
                                          float* __restrict__ C,
                                          int mt, int nt)
{
    __shared__ __align__(16) __half As[2][128][40];
    __shared__ __align__(16) __half Bs[2][128][40];

    const int tid = threadIdx.x, lane = tid & 31, wid = tid >> 5;
    const int wm = wid & 1, wn = wid >> 1;

    float acc[4][4][4] = {};

    const int ar  = tid >> 1;
    const int ac0 = (tid & 1) * 2;
    const __half* Abase = At + (size_t)(mt * 128 + ar) * 1024;
    const __half* Bbase = Bt + (size_t)(nt * 128 + ar) * 1024;

    const uint32_t sAs = smem_u32(As);
    const uint32_t sBs = smem_u32(Bs);
    const uint32_t dA = sAs + ar * 80 + ac0 * 16;
    const uint32_t dB = sBs + ar * 80 + ac0 * 16;

    const uint32_t a_row = wm * 64 + (lane & 15);
    const uint32_t a_col = (lane >> 4) << 3;
    const uint32_t b_row = wn * 32 + (lane & 7) + ((lane >> 4) << 3);
    const uint32_t b_col = ((lane >> 3) & 1) << 3;

#define ISSUE(kt) do {                                                        \
    const int _kt = (kt);                                                     \
    const int _seg = _kt >> 5, _kk = _kt & 31;                                \
    const __half* _a = Abase + (size_t)_seg * 4096 * 1024 + _kk * 32 + ac0 * 8; \
    const __half* _b = Bbase + _kk * 32 + ac0 * 8;                            \
    const uint32_t _da = dA + (_kt & 1) * 10240;                              \
    const uint32_t _db = dB + (_kt & 1) * 10240;                              \
    CP16(_da, _a); CP16(_da + 16, _a + 8);                                    \
    CP16(_db, _b); CP16(_db + 16, _b + 8);                                    \
    CP_COMMIT();                                                              \
} while (0)

    ISSUE(0);
    ISSUE(1);

    for (int kt = 0; kt < 64; kt++) {
        CP_WAIT1();
        __syncthreads();

        const uint32_t sa = sAs + (kt & 1) * 10240;
        const uint32_t sb = sBs + (kt & 1) * 10240;
#pragma unroll
        for (int ks = 0; ks < 32; ks += 16) {
            uint32_t af[4][4], bf[2][4];
#pragma unroll
            for (int mi = 0; mi < 4; mi++)
                ldsm4(af[mi], sa + ((a_row + mi * 16) * 40 + ks + a_col) * 2);
#pragma unroll
            for (int nj2 = 0; nj2 < 2; nj2++)
                ldsm4(bf[nj2], sb + ((b_row + nj2 * 16) * 40 + ks + b_col) * 2);
#pragma unroll
            for (int mi = 0; mi < 4; mi++)
#pragma unroll
                for (int nj = 0; nj < 4; nj++)
                    mma16816(acc[mi][nj], af[mi], &bf[nj >> 1][(nj & 1) * 2]);
        }
        __syncthreads();

        if (kt + 2 < 64) ISSUE(kt + 2);
        else CP_COMMIT();
    }
#undef ISSUE

#pragma unroll
    for (int mi = 0; mi < 4; mi++) {
        const int r0 = mt * 128 + wm * 64 + mi * 16 + (lane >> 2);
#pragma unroll
        for (int nj = 0; nj < 4; nj++) {
            const int col = nt * 128 + wn * 32 + nj * 8 + ((lane & 3) << 1);
            const float b0 = bias[col], b1 = bias[col + 1];
            float c0 = acc[mi][nj][0] + b0, c1 = acc[mi][nj][1] + b1;
            float c2 = acc[mi][nj][2] + b0, c3 = acc[mi][nj][3] + b1;
            if (MODE == 1) { c0 *= 0.125f; c1 *= 0.125f; c2 *= 0.125f; c3 *= 0.125f; }
            if (MODE == 0) {
                const int h = col >> 6, hd = col & 63;
                uint32_t hi, lo;
                {
                    const int b_ = r0 >> 11, s = r0 & 2047;
                    const size_t a = ((size_t)((b_ * 16 + h) * 2048 + s)) * 64 + hd;
                    split2h(c0, c1, hi, lo);
                    *(uint32_t*)(att_q[0] + a) = hi;
                    *(uint32_t*)(att_q[1] + a) = lo;
                }
                {
                    const int r1 = r0 + 8;
                    const int b_ = r1 >> 11, s = r1 & 2047;
                    const size_t a = ((size_t)((b_ * 16 + h) * 2048 + s)) * 64 + hd;
                    split2h(c2, c3, hi, lo);
                    *(uint32_t*)(att_q[0] + a) = hi;
                    *(uint32_t*)(att_q[1] + a) = lo;
                }
            } else if (MODE == 1) {
                const int h = col >> 6, hd = col & 63;
                const int b_0 = r0 >> 11, s0 = r0 & 2047;
                const int b_1 = (r0 + 8) >> 11, s1 = (r0 + 8) & 2047;
                *(uint32_t*)(att_k + ((size_t)((b_0 * 16 + h) * 2048 + s0)) * 64 + hd) = packh(c0, c1);
                *(uint32_t*)(att_k + ((size_t)((b_1 * 16 + h) * 2048 + s1)) * 64 + hd) = packh(c2, c3);
            } else if (MODE == 2) {
                const int h = col >> 6, hd = col & 63;
                const int b_0 = r0 >> 11, s0 = r0 & 2047;
                const int b_1 = (r0 + 8) >> 11, s1 = (r0 + 8) & 2047;
                *(float2*)(C + ((size_t)((b_0 * 16 + h) * 2048 + s0)) * 64 + hd) = {c0, c1};
                *(float2*)(C + ((size_t)((b_1 * 16 + h) * 2048 + s1)) * 64 + hd) = {c2, c3};
            } else {
                *(float2*)(C + (size_t)r0 * 1024 + col) = {c0, c1};
                *(float2*)(C + (size_t)(r0 + 8) * 1024 + col) = {c2, c3};
            }
        }
    }
}

__global__ __launch_bounds__(256, 2)
void qkv_gemm_kernel(const float* __restrict__ bq, const float* __restrict__ bk,
                     const float* __restrict__ bv)
{
    const int z = blockIdx.z;
    if (z == 0)      gemm_core<0>(a_act[0], b_wt[0], bq, nullptr, blockIdx.y, blockIdx.x);
    else if (z == 1) gemm_core<1>(a_act[1], b_wt[1], bk, nullptr, blockIdx.y, blockIdx.x);
    else             gemm_core<2>(a_act[2], b_wt[2], bv, g_v,     blockIdx.y, blockIdx.x);
}

__global__ __launch_bounds__(256, 2)
void oproj_gemm_kernel(const float* __restrict__ bo, float* __restrict__ out)
{
    gemm_core<3>(a_act[3], b_wt[3], bo, out, blockIdx.y, blockIdx.x);
}

// ---------------------------------------------------------------------------
// Tensor-core flash attention, v5: fp16 2-pass split. K/V need hi only.
// Grid (8 q-tiles, 32 bh), 256 threads (8 warps), warp = 32 Q rows.
// smem per stage: KH [64][72] + VH [64][72] = 18432 B; 2 stages = 36864 B.
// ---------------------------------------------------------------------------
constexpr int ATW = 72;
constexpr int ATT_SMEM = 2 * 2 * 64 * ATW * 2;            // 36864 B

__global__ __launch_bounds__(256, 1)
void attn_tc_kernel()
{
    extern __shared__ __half smb[];
    const uint32_t sb = smem_u32(smb);
    const int tid = threadIdx.x, lane = tid & 31, w = tid >> 5;
    const int bh = blockIdx.y;
    const int q0 = blockIdx.x * 256;

    // ---- Q fragments (hi/lo), staged through smem ----
    uint32_t qh[2][4][4], ql[2][4][4];
    {
        const int chunk = w >> 2;
        const int wrow  = (w & 3) * 32;
#pragma unroll
        for (int seg = 0; seg < 2; seg++) {
#pragma unroll
            for (int c = 0; c < 2; c++) {
                const __half* src = att_q[seg] + ((size_t)bh * 2048 + q0 + c * 128) * 64;
                for (int u = tid; u < 1024; u += 256) {
                    const int r = u >> 3, col = (u & 7) * 8;
                    *(uint4*)(smb + r * ATW + col) = *(const uint4*)(src + (size_t)r * 64 + col);
                }
                __syncthreads();
                if (chunk == c) {
#pragma unroll
                    for (int mi = 0; mi < 2; mi++) {
                        const uint32_t ab = sb +
                            (((wrow + mi * 16 + (lane & 15)) * ATW + ((lane >> 4) << 3)) << 1);
#pragma unroll
                        for (int kk = 0; kk < 4; kk++)
                            ldsm4(seg ? ql[mi][kk] : qh[mi][kk], ab + kk * 32);
                    }
                }
                __syncthreads();
            }
        }
    }

    // ---- KV pipeline: 2 arrays x 64 rows, 2 threads per row (64B each) ----
    const int arr = tid >> 7;              // 0:KH 1:VH
    const int rr0 = (tid >> 1) & 63;
    const int hf  = tid & 1;
    const __half* src0;
    size_t step;
    if (arr == 0) { src0 = att_k  + ((size_t)bh * 2048 + rr0) * 64 + hf * 32;  step = 4096; }
    else          { src0 = att_vt + ((size_t)bh * 64 + rr0) * 2048 + hf * 32;  step = 64;   }
    const uint32_t dst0 = sb + arr * 9216 + rr0 * 144 + hf * 64;

#define AISSUE(it) do {                                                       \
    const __half* _s = src0 + (size_t)(it) * step;                            \
    const uint32_t _d = dst0 + ((it) & 1) * 18432;                            \
    CP16(_d, _s); CP16(_d + 16, _s + 8);                                      \
    CP16(_d + 32, _s + 16); CP16(_d + 48, _s + 24);                           \
    CP_COMMIT();                                                              \
} while (0)

    AISSUE(0);
    AISSUE(1);

    const uint32_t brow  = (lane & 7) + ((lane >> 4) << 3);
    const uint32_t bcol2 = (((lane >> 3) & 1) << 3) * 2;
    const uint32_t boff  = brow * 144 + bcol2;

    float o[2][8][4] = {};
    float m[2][2], l[2][2];
#pragma unroll
    for (int mi = 0; mi < 2; mi++) { m[mi][0] = m[mi][1] = -1e30f; l[mi][0] = l[mi][1] = 0.0f; }

    for (int it = 0; it < 32; it++) {
        CP_WAIT1();
        __syncthreads();

        const uint32_t bufb = sb + (it & 1) * 18432;
        const uint32_t KH = bufb, VH = bufb + 9216;

        // ---- S = qh*KH + ql*KH (16 pipelined ldsm steps) ----
        float s[2][8][4] = {};
        {
            uint32_t bfb[2][4];
            ldsm4(bfb[0], KH + boff);
#pragma unroll
            for (int i = 0; i < 16; i++) {
                if (i + 1 < 16) {
                    const int j = i + 1, jk = j >> 2, jg = j & 3;
                    ldsm4(bfb[j & 1], KH + (jg * 16) * 144 + jk * 32 + boff);
                }
                const uint32_t* bf = bfb[i & 1];
                const int kk = i >> 2, g = i & 3;
#pragma unroll
                for (int mi = 0; mi < 2; mi++) {
                    mma16816(s[mi][2 * g],     qh[mi][kk], bf);
                    mma16816(s[mi][2 * g + 1], qh[mi][kk], bf + 2);
                    mma16816(s[mi][2 * g],     ql[mi][kk], bf);
                    mma16816(s[mi][2 * g + 1], ql[mi][kk], bf + 2);
                }
            }
        }

        // Prefetch first V fragment; latency hides behind softmax.
        uint32_t bfv[2][4];
        ldsm4(bfv[0], VH + boff);

        // ---- online softmax + P split (fp16 hi/lo) ----
        uint32_t ph[2][4][4], pl[2][4][4];
#pragma unroll
        for (int mi = 0; mi < 2; mi++) {
            float mx0 = -1e30f, mx1 = -1e30f;
#pragma unroll
            for (int nj = 0; nj < 8; nj++) {
                mx0 = fmaxf(mx0, fmaxf(s[mi][nj][0], s[mi][nj][1]));
                mx1 = fmaxf(mx1, fmaxf(s[mi][nj][2], s[mi][nj][3]));
            }
            mx0 = fmaxf(mx0, __shfl_xor_sync(0xffffffffu, mx0, 1));
            mx0 = fmaxf(mx0, __shfl_xor_sync(0xffffffffu, mx0, 2));
            mx1 = fmaxf(mx1, __shfl_xor_sync(0xffffffffu, mx1, 1));
            mx1 = fmaxf(mx1, __shfl_xor_sync(0xffffffffu, mx1, 2));
            const float mn0 = fmaxf(m[mi][0], mx0), mn1 = fmaxf(m[mi][1], mx1);
            const float f0 = __expf(m[mi][0] - mn0), f1 = __expf(m[mi][1] - mn1);
            m[mi][0] = mn0; m[mi][1] = mn1;

            float la0 = 0.0f, la1 = 0.0f;
#pragma unroll
            for (int nj = 0; nj < 8; nj++) {
                float pe[4], pel[4];
#pragma unroll
                for (int e = 0; e < 4; e++) {
                    const float p = __expf(s[mi][nj][e] - ((e < 2) ? mn0 : mn1));
                    if (e < 2) la0 += p; else la1 += p;
                    const __half hb = __float2half_rn(p);
                    pe[e]  = p;
                    pel[e] = p - __half2float(hb);
                }
                const int kk = nj >> 1, sel = (nj & 1) * 2;
                ph[mi][kk][sel]     = packh(pe[0], pe[1]);
                ph[mi][kk][sel + 1] = packh(pe[2], pe[3]);
                pl[mi][kk][sel]     = packh(pel[0], pel[1]);
                pl[mi][kk][sel + 1] = packh(pel[2], pel[3]);
            }
            la0 += __shfl_xor_sync(0xffffffffu, la0, 1);
            la0 += __shfl_xor_sync(0xffffffffu, la0, 2);
            la1 += __shfl_xor_sync(0xffffffffu, la1, 1);
            la1 += __shfl_xor_sync(0xffffffffu, la1, 2);
            l[mi][0] = l[mi][0] * f0 + la0;
            l[mi][1] = l[mi][1] * f1 + la1;
#pragma unroll
            for (int nj = 0; nj < 8; nj++) {
                o[mi][nj][0] *= f0; o[mi][nj][1] *= f0;
                o[mi][nj][2] *= f1; o[mi][nj][3] *= f1;
            }
        }

        // ---- O += ph*VH + pl*VH (16 pipelined ldsm steps) ----
#pragma unroll
        for (int i = 0; i < 16; i++) {
            if (i + 1 < 16) {
                const int j = i + 1, jk = j >> 2, jg = j & 3;
                ldsm4(bfv[j & 1], VH + (jg * 16) * 144 + jk * 32 + boff);
            }
            const uint32_t* bf = bfv[i & 1];
            const int kk = i >> 2, g = i & 3;
#pragma unroll
            for (int mi = 0; mi < 2; mi++) {
                mma16816(o[mi][2 * g],     ph[mi][kk], bf);
                mma16816(o[mi][2 * g + 1], ph[mi][kk], bf + 2);
                mma16816(o[mi][2 * g],     pl[mi][kk], bf);
                mma16816(o[mi][2 * g + 1], pl[mi][kk], bf + 2);
            }
        }

        __syncthreads();
        if (it + 2 < 32) AISSUE(it + 2);
        else CP_COMMIT();
    }
#undef AISSUE

    // ---- epilogue: write split-fp16 ctx into a_act[3] ----
    const int b = bh >> 4, h = bh & 15;
    __half* HI = a_act[3];
    __half* LO = a_act[3] + (size_t)4096 * 1024;
#pragma unroll
    for (int mi = 0; mi < 2; mi++) {
        const float inv0 = 1.0f / l[mi][0], inv1 = 1.0f / l[mi][1];
        const int row0 = b * 2048 + q0 + w * 32 + mi * 16 + (lane >> 2);
#pragma unroll
        for (int nj = 0; nj < 8; nj++) {
            const int col = h * 64 + nj * 8 + ((lane & 3) << 1);
            uint32_t hi, lo;
            split2h(o[mi][nj][0] * inv0, o[mi][nj][1] * inv0, hi, lo);
            *(uint32_t*)(HI + (size_t)row0 * 1024 + col) = hi;
            *(uint32_t*)(LO + (size_t)row0 * 1024 + col) = lo;
            split2h(o[mi][nj][2] * inv1, o[mi][nj][3] * inv1, hi, lo);
            *(uint32_t*)(HI + (size_t)(row0 + 8) * 1024 + col) = hi;
            *(uint32_t*)(LO + (size_t)(row0 + 8) * 1024 + col) = lo;
        }
    }
}

// ---------------------------------------------------------------------------
extern "C" void kernel_launch(void* const* d_in, const int* in_sizes, int n_in,
                              void* d_out, int out_size)
{
    (void)in_sizes; (void)n_in; (void)out_size;
    const float* q  = (const float*)d_in[0];
    const float* k  = (const float*)d_in[1];
    const float* v  = (const float*)d_in[2];
    const float* Wq = (const float*)d_in[3];
    const float* bq = (const float*)d_in[4];
    const float* Wk = (const float*)d_in[5];
    const float* bk = (const float*)d_in[6];
    const float* Wv = (const float*)d_in[7];
    const float* bv = (const float*)d_in[8];
    const float* Wo = (const float*)d_in[9];
    const float* bo = (const float*)d_in[10];
    float* out = (float*)d_out;

    cudaFuncSetAttribute(attn_tc_kernel, cudaFuncAttributeMaxDynamicSharedMemorySize,
                         ATT_SMEM);

    conv_w_kernel<<<dim3(1024, 1, 4), 256>>>(Wq, Wk, Wv, Wo);
    conv_acts_kernel<<<dim3(2048, 1, 3), 256>>>(q, k, v);

    qkv_gemm_kernel<<<dim3(8, 32, 3), 256>>>(bq, bk, bv);

    conv_attn_v_kernel<<<dim3(32, 32), 256>>>();
    attn_tc_kernel<<<dim3(8, 32), 256, ATT_SMEM>>>();

    oproj_gemm_kernel<<<dim3(8, 32), 256>>>(bo, out);
}

// round 9
// speedup vs baseline: 3.5103x; 1.4875x over previous
#include <cuda_runtime.h>
#include <cuda_fp16.h>
#include <cstdint>

// Problem constants
constexpr int Bb  = 2;
constexpr int Ss  = 2048;
constexpr int Dd  = 1024;
constexpr int Hh  = 16;
constexpr int HDd = 64;

// ---------------------------------------------------------------------------
// Scratch (allocation-free: __device__ globals)
// ---------------------------------------------------------------------------
__device__ float g_v[Bb * Hh * Ss * HDd];    // [B,H,S,HD] fp32 (for V transpose)

// fp16 GEMM operands (row-major, K contiguous).
// a_act[0..2]: q,k,v inputs, hi only used. a_act[3]: ctx hi+lo (2-pass oproj).
__device__ __half a_act[4][2 * 4096 * 1024];
__device__ __half b_wt[4][1024 * 1024];

// fp16 attention operands (all hi-only)
__device__ __half att_q[(size_t)32 * 2048 * 64];      // [bh][s][hd]
__device__ __half att_k[(size_t)32 * 2048 * 64];      // [bh][s][hd], x0.125 folded
__device__ __half att_vt[(size_t)32 * 64 * 2048];     // [bh][hd][s]

// ---------------------------------------------------------------------------
// Helpers
// ---------------------------------------------------------------------------
__device__ __forceinline__ uint32_t smem_u32(const void* p) {
    uint32_t a;
    asm("{ .reg .u64 t; cvta.to.shared.u64 t, %1; cvt.u32.u64 %0, t; }"
        : "=r"(a) : "l"(p));
    return a;
}

#define CP16(dst, src) \
    asm volatile("cp.async.cg.shared.global [%0], [%1], 16;" :: "r"(dst), "l"(src))
#define CP_COMMIT() asm volatile("cp.async.commit_group;" ::: "memory")
#define CP_WAIT1()  asm volatile("cp.async.wait_group 1;" ::: "memory")

__device__ __forceinline__ void ldsm4(uint32_t* r, uint32_t addr) {
    asm volatile("ldmatrix.sync.aligned.m8n8.x4.shared.b16 {%0,%1,%2,%3}, [%4];"
        : "=r"(r[0]), "=r"(r[1]), "=r"(r[2]), "=r"(r[3]) : "r"(addr));
}

__device__ __forceinline__ void mma16816(float* c, const uint32_t* a, const uint32_t* b) {
    asm volatile(
        "mma.sync.aligned.m16n8k16.row.col.f32.f16.f16.f32 "
        "{%0,%1,%2,%3}, {%4,%5,%6,%7}, {%8,%9}, {%0,%1,%2,%3};"
        : "+f"(c[0]), "+f"(c[1]), "+f"(c[2]), "+f"(c[3])
        : "r"(a[0]), "r"(a[1]), "r"(a[2]), "r"(a[3]), "r"(b[0]), "r"(b[1]));
}

__device__ __forceinline__ uint32_t packh(float x, float y) {
    __half2 t = __floats2half2_rn(x, y);
    return *(uint32_t*)&t;
}

__device__ __forceinline__ void split2h(float x, float y, uint32_t& hi, uint32_t& lo) {
    hi = packh(x, y);
    __half2 hb = *(__half2*)&hi;
    lo = packh(x - __half2float(hb.x), y - __half2float(hb.y));
}

// ---------------------------------------------------------------------------
// Conversions
// ---------------------------------------------------------------------------
__global__ __launch_bounds__(256)
void conv_acts_kernel(const float* __restrict__ q, const float* __restrict__ k,
                      const float* __restrict__ v)
{
    const int z = blockIdx.z;
    const float* src = (z == 0) ? q : (z == 1) ? k : v;
    const size_t base = ((size_t)blockIdx.x * 256 + threadIdx.x) * 8;
    float4 f0 = *(const float4*)(src + base);
    float4 f1 = *(const float4*)(src + base + 4);
    float xs[8] = {f0.x, f0.y, f0.z, f0.w, f1.x, f1.y, f1.z, f1.w};
    union { uint4 u4; __half h[8]; } H;
#pragma unroll
    for (int j = 0; j < 8; j++) H.h[j] = __float2half_rn(xs[j]);
    *(uint4*)(a_act[z] + base) = H.u4;
}

__global__ __launch_bounds__(256)
void conv_w_kernel(const float* __restrict__ Wq, const float* __restrict__ Wk,
                   const float* __restrict__ Wv, const float* __restrict__ Wo)
{
    const int w = blockIdx.z;
    const float* W = (w == 0) ? Wq : (w == 1) ? Wk : (w == 2) ? Wv : Wo;
    const int k = blockIdx.x;
    __half* hi = b_wt[w];
#pragma unroll
    for (int j = 0; j < 4; j++) {
        const int n = threadIdx.x * 4 + j;
        const size_t idx = (w < 3)
            ? ((size_t)(n >> 6) << 16) + (size_t)k * 64 + (n & 63)
            : (size_t)k * 1024 + n;
        hi[(size_t)n * 1024 + k] = __float2half_rn(W[idx]);
    }
}

// V transpose prep: g_v [bh][s][64] -> att_vt [bh][hd][s]
__global__ __launch_bounds__(256)
void conv_attn_v_kernel()
{
    __shared__ float vs[64][65];
    const int bh = blockIdx.y, st = blockIdx.x, t = threadIdx.x;
    const size_t base = ((size_t)bh * 2048 + st * 64) * 64;

    for (int u = t; u < 1024; u += 256) {
        const int s = u >> 4, hd = (u & 15) * 4;
        float4 f = *(const float4*)(g_v + base + (size_t)s * 64 + hd);
        vs[s][hd] = f.x; vs[s][hd + 1] = f.y; vs[s][hd + 2] = f.z; vs[s][hd + 3] = f.w;
    }
    __syncthreads();
    for (int u = t; u < 1024; u += 256) {
        const int hd = u >> 4, s0 = (u & 15) * 4;
        union { uint2 u2; __half h[4]; } H;
#pragma unroll
        for (int j = 0; j < 4; j++)
            H.h[j] = __float2half_rn(vs[s0 + j][hd]);
        const size_t o = ((size_t)bh * 64 + hd) * 2048 + st * 64 + s0;
        *(uint2*)(att_vt + o) = H.u2;
    }
}

// ---------------------------------------------------------------------------
// mma.sync fp16 GEMM. PASSES: 1 = hi only (K_eff 1024), 2 = A hi+lo (K_eff 2048).
// MODE: 0 = att_q fp16, 1 = att_k fp16 x0.125, 2 = g_v fp32 scatter, 3 = fp32 out.
// ---------------------------------------------------------------------------
template<int MODE, int PASSES>
__device__ __forceinline__ void gemm_core(const __half* __restrict__ At,
                                          const __half* __restrict__ Bt,
                                          const float* __restrict__ bias,
                                          float* __restrict__ C,
                                          int mt, int nt)
{
    __shared__ __align__(16) __half As[2][128][40];
    __shared__ __align__(16) __half Bs[2][128][40];

    const int tid = threadIdx.x, lane = tid & 31, wid = tid >> 5;
    const int wm = wid & 1, wn = wid >> 1;
    constexpr int NKT = PASSES * 32;

    float acc[4][4][4] = {};

    const int ar  = tid >> 1;
    const int ac0 = (tid & 1) * 2;
    const __half* Abase = At + (size_t)(mt * 128 + ar) * 1024;
    const __half* Bbase = Bt + (size_t)(nt * 128 + ar) * 1024;

    const uint32_t sAs = smem_u32(As);
    const uint32_t sBs = smem_u32(Bs);
    const uint32_t dA = sAs + ar * 80 + ac0 * 16;
    const uint32_t dB = sBs + ar * 80 + ac0 * 16;

    const uint32_t a_row = wm * 64 + (lane & 15);
    const uint32_t a_col = (lane >> 4) << 3;
    const uint32_t b_row = wn * 32 + (lane & 7) + ((lane >> 4) << 3);
    const uint32_t b_col = ((lane >> 3) & 1) << 3;

#define ISSUE(kt) do {                                                        \
    const int _kt = (kt);                                                     \
    const int _seg = _kt >> 5, _kk = _kt & 31;                                \
    const __half* _a = Abase + (size_t)_seg * 4096 * 1024 + _kk * 32 + ac0 * 8; \
    const __half* _b = Bbase + _kk * 32 + ac0 * 8;                            \
    const uint32_t _da = dA + (_kt & 1) * 10240;                              \
    const uint32_t _db = dB + (_kt & 1) * 10240;                              \
    CP16(_da, _a); CP16(_da + 16, _a + 8);                                    \
    CP16(_db, _b); CP16(_db + 16, _b + 8);                                    \
    CP_COMMIT();                                                              \
} while (0)

    ISSUE(0);
    ISSUE(1);

    for (int kt = 0; kt < NKT; kt++) {
        CP_WAIT1();
        __syncthreads();

        const uint32_t sa = sAs + (kt & 1) * 10240;
        const uint32_t sb = sBs + (kt & 1) * 10240;
#pragma unroll
        for (int ks = 0; ks < 32; ks += 16) {
            uint32_t af[4][4], bf[2][4];
#pragma unroll
            for (int mi = 0; mi < 4; mi++)
                ldsm4(af[mi], sa + ((a_row + mi * 16) * 40 + ks + a_col) * 2);
#pragma unroll
            for (int nj2 = 0; nj2 < 2; nj2++)
                ldsm4(bf[nj2], sb + ((b_row + nj2 * 16) * 40 + ks + b_col) * 2);
#pragma unroll
            for (int mi = 0; mi < 4; mi++)
#pragma unroll
                for (int nj = 0; nj < 4; nj++)
                    mma16816(acc[mi][nj], af[mi], &bf[nj >> 1][(nj & 1) * 2]);
        }
        __syncthreads();

        if (kt + 2 < NKT) ISSUE(kt + 2);
        else CP_COMMIT();
    }
#undef ISSUE

#pragma unroll
    for (int mi = 0; mi < 4; mi++) {
        const int r0 = mt * 128 + wm * 64 + mi * 16 + (lane >> 2);
#pragma unroll
        for (int nj = 0; nj < 4; nj++) {
            const int col = nt * 128 + wn * 32 + nj * 8 + ((lane & 3) << 1);
            const float b0 = bias[col], b1 = bias[col + 1];
            float c0 = acc[mi][nj][0] + b0, c1 = acc[mi][nj][1] + b1;
            float c2 = acc[mi][nj][2] + b0, c3 = acc[mi][nj][3] + b1;
            if (MODE == 1) { c0 *= 0.125f; c1 *= 0.125f; c2 *= 0.125f; c3 *= 0.125f; }
            if (MODE <= 1) {
                __half* D = (MODE == 0) ? att_q : att_k;
                const int h = col >> 6, hd = col & 63;
                const int b_0 = r0 >> 11, s0 = r0 & 2047;
                const int b_1 = (r0 + 8) >> 11, s1 = (r0 + 8) & 2047;
                *(uint32_t*)(D + ((size_t)((b_0 * 16 + h) * 2048 + s0)) * 64 + hd) = packh(c0, c1);
                *(uint32_t*)(D + ((size_t)((b_1 * 16 + h) * 2048 + s1)) * 64 + hd) = packh(c2, c3);
            } else if (MODE == 2) {
                const int h = col >> 6, hd = col & 63;
                const int b_0 = r0 >> 11, s0 = r0 & 2047;
                const int b_1 = (r0 + 8) >> 11, s1 = (r0 + 8) & 2047;
                *(float2*)(C + ((size_t)((b_0 * 16 + h) * 2048 + s0)) * 64 + hd) = {c0, c1};
                *(float2*)(C + ((size_t)((b_1 * 16 + h) * 2048 + s1)) * 64 + hd) = {c2, c3};
            } else {
                *(float2*)(C + (size_t)r0 * 1024 + col) = {c0, c1};
                *(float2*)(C + (size_t)(r0 + 8) * 1024 + col) = {c2, c3};
            }
        }
    }
}

__global__ __launch_bounds__(256, 2)
void qkv_gemm_kernel(const float* __restrict__ bq, const float* __restrict__ bk,
                     const float* __restrict__ bv)
{
    const int z = blockIdx.z;
    if (z == 0)      gemm_core<0, 1>(a_act[0], b_wt[0], bq, nullptr, blockIdx.y, blockIdx.x);
    else if (z == 1) gemm_core<1, 1>(a_act[1], b_wt[1], bk, nullptr, blockIdx.y, blockIdx.x);
    else             gemm_core<2, 1>(a_act[2], b_wt[2], bv, g_v,     blockIdx.y, blockIdx.x);
}

__global__ __launch_bounds__(256, 2)
void oproj_gemm_kernel(const float* __restrict__ bo, float* __restrict__ out)
{
    gemm_core<3, 2>(a_act[3], b_wt[3], bo, out, blockIdx.y, blockIdx.x);
}

// ---------------------------------------------------------------------------
// Tensor-core flash attention, v6: single-pass fp16 on both matmuls.
// Grid (8 q-tiles, 32 bh), 256 threads (8 warps), warp = 32 Q rows.
// Output ctx written as hi/lo fp16 into a_act[3] (2-pass oproj keeps precision).
// ---------------------------------------------------------------------------
constexpr int ATW = 72;
constexpr int ATT_SMEM = 2 * 2 * 64 * ATW * 2;            // 36864 B

__global__ __launch_bounds__(256, 1)
void attn_tc_kernel()
{
    extern __shared__ __half smb[];
    const uint32_t sb = smem_u32(smb);
    const int tid = threadIdx.x, lane = tid & 31, w = tid >> 5;
    const int bh = blockIdx.y;
    const int q0 = blockIdx.x * 256;

    // ---- Q fragments (hi only), staged through smem ----
    uint32_t qh[2][4][4];
    {
        const int chunk = w >> 2;
        const int wrow  = (w & 3) * 32;
#pragma unroll
        for (int c = 0; c < 2; c++) {
            const __half* src = att_q + ((size_t)bh * 2048 + q0 + c * 128) * 64;
            for (int u = tid; u < 1024; u += 256) {
                const int r = u >> 3, col = (u & 7) * 8;
                *(uint4*)(smb + r * ATW + col) = *(const uint4*)(src + (size_t)r * 64 + col);
            }
            __syncthreads();
            if (chunk == c) {
#pragma unroll
                for (int mi = 0; mi < 2; mi++) {
                    const uint32_t ab = sb +
                        (((wrow + mi * 16 + (lane & 15)) * ATW + ((lane >> 4) << 3)) << 1);
#pragma unroll
                    for (int kk = 0; kk < 4; kk++)
                        ldsm4(qh[mi][kk], ab + kk * 32);
                }
            }
            __syncthreads();
        }
    }

    // ---- KV pipeline: 2 arrays x 64 rows, 2 threads per row ----
    const int arr = tid >> 7;              // 0:KH 1:VH
    const int rr0 = (tid >> 1) & 63;
    const int hf  = tid & 1;
    const __half* src0;
    size_t step;
    if (arr == 0) { src0 = att_k  + ((size_t)bh * 2048 + rr0) * 64 + hf * 32;  step = 4096; }
    else          { src0 = att_vt + ((size_t)bh * 64 + rr0) * 2048 + hf * 32;  step = 64;   }
    const uint32_t dst0 = sb + arr * 9216 + rr0 * 144 + hf * 64;

#define AISSUE(it) do {                                                       \
    const __half* _s = src0 + (size_t)(it) * step;                            \
    const uint32_t _d = dst0 + ((it) & 1) * 18432;                            \
    CP16(_d, _s); CP16(_d + 16, _s + 8);                                      \
    CP16(_d + 32, _s + 16); CP16(_d + 48, _s + 24);                           \
    CP_COMMIT();                                                              \
} while (0)

    AISSUE(0);
    AISSUE(1);

    const uint32_t brow  = (lane & 7) + ((lane >> 4) << 3);
    const uint32_t bcol2 = (((lane >> 3) & 1) << 3) * 2;
    const uint32_t boff  = brow * 144 + bcol2;

    float o[2][8][4] = {};
    float m[2][2], l[2][2];
#pragma unroll
    for (int mi = 0; mi < 2; mi++) { m[mi][0] = m[mi][1] = -1e30f; l[mi][0] = l[mi][1] = 0.0f; }

    for (int it = 0; it < 32; it++) {
        CP_WAIT1();
        __syncthreads();

        const uint32_t bufb = sb + (it & 1) * 18432;
        const uint32_t KH = bufb, VH = bufb + 9216;

        // ---- S = qh * KH (16 pipelined ldsm steps) ----
        float s[2][8][4] = {};
        {
            uint32_t bfb[2][4];
            ldsm4(bfb[0], KH + boff);
#pragma unroll
            for (int i = 0; i < 16; i++) {
                if (i + 1 < 16) {
                    const int j = i + 1, jk = j >> 2, jg = j & 3;
                    ldsm4(bfb[j & 1], KH + (jg * 16) * 144 + jk * 32 + boff);
                }
                const uint32_t* bf = bfb[i & 1];
                const int kk = i >> 2, g = i & 3;
#pragma unroll
                for (int mi = 0; mi < 2; mi++) {
                    mma16816(s[mi][2 * g],     qh[mi][kk], bf);
                    mma16816(s[mi][2 * g + 1], qh[mi][kk], bf + 2);
                }
            }
        }

        // Prefetch first V fragment; latency hides behind softmax.
        uint32_t bfv[2][4];
        ldsm4(bfv[0], VH + boff);

        // ---- online softmax; P rounded to fp16, l computed from ROUNDED p ----
        uint32_t ph[2][4][4];
#pragma unroll
        for (int mi = 0; mi < 2; mi++) {
            float mx0 = -1e30f, mx1 = -1e30f;
#pragma unroll
            for (int nj = 0; nj < 8; nj++) {
                mx0 = fmaxf(mx0, fmaxf(s[mi][nj][0], s[mi][nj][1]));
                mx1 = fmaxf(mx1, fmaxf(s[mi][nj][2], s[mi][nj][3]));
            }
            mx0 = fmaxf(mx0, __shfl_xor_sync(0xffffffffu, mx0, 1));
            mx0 = fmaxf(mx0, __shfl_xor_sync(0xffffffffu, mx0, 2));
            mx1 = fmaxf(mx1, __shfl_xor_sync(0xffffffffu, mx1, 1));
            mx1 = fmaxf(mx1, __shfl_xor_sync(0xffffffffu, mx1, 2));
            const float mn0 = fmaxf(m[mi][0], mx0), mn1 = fmaxf(m[mi][1], mx1);
            const float f0 = __expf(m[mi][0] - mn0), f1 = __expf(m[mi][1] - mn1);
            m[mi][0] = mn0; m[mi][1] = mn1;

            float la0 = 0.0f, la1 = 0.0f;
#pragma unroll
            for (int nj = 0; nj < 8; nj++) {
                const float p0 = __expf(s[mi][nj][0] - mn0);
                const float p1 = __expf(s[mi][nj][1] - mn0);
                const float p2 = __expf(s[mi][nj][2] - mn1);
                const float p3 = __expf(s[mi][nj][3] - mn1);
                const uint32_t u01 = packh(p0, p1);
                const uint32_t u23 = packh(p2, p3);
                const __half2 h01 = *(const __half2*)&u01;
                const __half2 h23 = *(const __half2*)&u23;
                la0 += __half2float(h01.x) + __half2float(h01.y);
                la1 += __half2float(h23.x) + __half2float(h23.y);
                const int kk = nj >> 1, sel = (nj & 1) * 2;
                ph[mi][kk][sel]     = u01;
                ph[mi][kk][sel + 1] = u23;
            }
            la0 += __shfl_xor_sync(0xffffffffu, la0, 1);
            la0 += __shfl_xor_sync(0xffffffffu, la0, 2);
            la1 += __shfl_xor_sync(0xffffffffu, la1, 1);
            la1 += __shfl_xor_sync(0xffffffffu, la1, 2);
            l[mi][0] = l[mi][0] * f0 + la0;
            l[mi][1] = l[mi][1] * f1 + la1;
#pragma unroll
            for (int nj = 0; nj < 8; nj++) {
                o[mi][nj][0] *= f0; o[mi][nj][1] *= f0;
                o[mi][nj][2] *= f1; o[mi][nj][3] *= f1;
            }
        }

        // ---- O += ph * VH (16 pipelined ldsm steps) ----
#pragma unroll
        for (int i = 0; i < 16; i++) {
            if (i + 1 < 16) {
                const int j = i + 1, jk = j >> 2, jg = j & 3;
                ldsm4(bfv[j & 1], VH + (jg * 16) * 144 + jk * 32 + boff);
            }
            const uint32_t* bf = bfv[i & 1];
            const int kk = i >> 2, g = i & 3;
#pragma unroll
            for (int mi = 0; mi < 2; mi++) {
                mma16816(o[mi][2 * g],     ph[mi][kk], bf);
                mma16816(o[mi][2 * g + 1], ph[mi][kk], bf + 2);
            }
        }

        __syncthreads();
        if (it + 2 < 32) AISSUE(it + 2);
        else CP_COMMIT();
    }
#undef AISSUE

    // ---- epilogue: write split-fp16 ctx into a_act[3] (hi + lo) ----
    const int b = bh >> 4, h = bh & 15;
    __half* HI = a_act[3];
    __half* LO = a_act[3] + (size_t)4096 * 1024;
#pragma unroll
    for (int mi = 0; mi < 2; mi++) {
        const float inv0 = 1.0f / l[mi][0], inv1 = 1.0f / l[mi][1];
        const int row0 = b * 2048 + q0 + w * 32 + mi * 16 + (lane >> 2);
#pragma unroll
        for (int nj = 0; nj < 8; nj++) {
            const int col = h * 64 + nj * 8 + ((lane & 3) << 1);
            uint32_t hi, lo;
            split2h(o[mi][nj][0] * inv0, o[mi][nj][1] * inv0, hi, lo);
            *(uint32_t*)(HI + (size_t)row0 * 1024 + col) = hi;
            *(uint32_t*)(LO + (size_t)row0 * 1024 + col) = lo;
            split2h(o[mi][nj][2] * inv1, o[mi][nj][3] * inv1, hi, lo);
            *(uint32_t*)(HI + (size_t)(row0 + 8) * 1024 + col) = hi;
            *(uint32_t*)(LO + (size_t)(row0 + 8) * 1024 + col) = lo;
        }
    }
}

// ---------------------------------------------------------------------------
extern "C" void kernel_launch(void* const* d_in, const int* in_sizes, int n_in,
                              void* d_out, int out_size)
{
    (void)in_sizes; (void)n_in; (void)out_size;
    const float* q  = (const float*)d_in[0];
    const float* k  = (const float*)d_in[1];
    const float* v  = (const float*)d_in[2];
    const float* Wq = (const float*)d_in[3];
    const float* bq = (const float*)d_in[4];
    const float* Wk = (const float*)d_in[5];
    const float* bk = (const float*)d_in[6];
    const float* Wv = (const float*)d_in[7];
    const float* bv = (const float*)d_in[8];
    const float* Wo = (const float*)d_in[9];
    const float* bo = (const float*)d_in[10];
    float* out = (float*)d_out;

    cudaFuncSetAttribute(attn_tc_kernel, cudaFuncAttributeMaxDynamicSharedMemorySize,
                         ATT_SMEM);

    conv_w_kernel<<<dim3(1024, 1, 4), 256>>>(Wq, Wk, Wv, Wo);
    conv_acts_kernel<<<dim3(2048, 1, 3), 256>>>(q, k, v);

    qkv_gemm_kernel<<<dim3(8, 32, 3), 256>>>(bq, bk, bv);

    conv_attn_v_kernel<<<dim3(32, 32), 256>>>();
    attn_tc_kernel<<<dim3(8, 32), 256, ATT_SMEM>>>();

    oproj_gemm_kernel<<<dim3(8, 32), 256>>>(bo, out);
}

// round 10
// speedup vs baseline: 3.9784x; 1.1334x over previous
#include <cuda_runtime.h>
#include <cuda_fp16.h>
#include <cstdint>

// Problem constants
constexpr int Bb  = 2;
constexpr int Ss  = 2048;
constexpr int Dd  = 1024;
constexpr int Hh  = 16;
constexpr int HDd = 64;

// 0.125 * log2(e): folds the softmax scale AND the exp->exp2 conversion into K.
#define KSCL 0.1803368801111204f

// ---------------------------------------------------------------------------
// Scratch (allocation-free: __device__ globals)
// ---------------------------------------------------------------------------
// fp16 GEMM operands (row-major, K contiguous). a_act[3] = ctx (hi only).
__device__ __half a_act[4][2 * 4096 * 1024];
__device__ __half b_wt[4][1024 * 1024];

// fp16 attention operands
__device__ __half att_q[(size_t)32 * 2048 * 64];      // [bh][s][hd]
__device__ __half att_k[(size_t)32 * 2048 * 64];      // [bh][s][hd], x KSCL folded
__device__ __half att_v[(size_t)32 * 2048 * 64];      // [bh][s][hd]
__device__ __half att_vt[(size_t)32 * 64 * 2048];     // [bh][hd][s]

// ---------------------------------------------------------------------------
// Helpers
// ---------------------------------------------------------------------------
__device__ __forceinline__ uint32_t smem_u32(const void* p) {
    uint32_t a;
    asm("{ .reg .u64 t; cvta.to.shared.u64 t, %1; cvt.u32.u64 %0, t; }"
        : "=r"(a) : "l"(p));
    return a;
}

#define CP16(dst, src) \
    asm volatile("cp.async.cg.shared.global [%0], [%1], 16;" :: "r"(dst), "l"(src))
#define CP_COMMIT() asm volatile("cp.async.commit_group;" ::: "memory")
#define CP_WAIT1()  asm volatile("cp.async.wait_group 1;" ::: "memory")

__device__ __forceinline__ void ldsm4(uint32_t* r, uint32_t addr) {
    asm volatile("ldmatrix.sync.aligned.m8n8.x4.shared.b16 {%0,%1,%2,%3}, [%4];"
        : "=r"(r[0]), "=r"(r[1]), "=r"(r[2]), "=r"(r[3]) : "r"(addr));
}

__device__ __forceinline__ void mma16816(float* c, const uint32_t* a, const uint32_t* b) {
    asm volatile(
        "mma.sync.aligned.m16n8k16.row.col.f32.f16.f16.f32 "
        "{%0,%1,%2,%3}, {%4,%5,%6,%7}, {%8,%9}, {%0,%1,%2,%3};"
        : "+f"(c[0]), "+f"(c[1]), "+f"(c[2]), "+f"(c[3])
        : "r"(a[0]), "r"(a[1]), "r"(a[2]), "r"(a[3]), "r"(b[0]), "r"(b[1]));
}

__device__ __forceinline__ uint32_t packh(float x, float y) {
    __half2 t = __floats2half2_rn(x, y);
    return *(uint32_t*)&t;
}

__device__ __forceinline__ float fexp2(float x) {
    float r;
    asm("ex2.approx.f32 %0, %1;" : "=f"(r) : "f"(x));
    return r;
}

// ---------------------------------------------------------------------------
// Fused conversion kernel. Grid (2048, 1, 7):
// z 0..2: activations q,k,v fp32 -> fp16 (blockIdx.x covers 4096x1024 / 2048).
// z 3..6: weights Wq,Wk,Wv,Wo -> B^T [n][k] fp16 (blockIdx.x = k, guard <1024).
// ---------------------------------------------------------------------------
__global__ __launch_bounds__(256)
void conv_all_kernel(const float* __restrict__ q, const float* __restrict__ k,
                     const float* __restrict__ v,
                     const float* __restrict__ Wq, const float* __restrict__ Wk,
                     const float* __restrict__ Wv, const float* __restrict__ Wo)
{
    const int z = blockIdx.z;
    if (z < 3) {
        const float* src = (z == 0) ? q : (z == 1) ? k : v;
        const size_t base = ((size_t)blockIdx.x * 256 + threadIdx.x) * 8;
        float4 f0 = *(const float4*)(src + base);
        float4 f1 = *(const float4*)(src + base + 4);
        float xs[8] = {f0.x, f0.y, f0.z, f0.w, f1.x, f1.y, f1.z, f1.w};
        union { uint4 u4; __half h[8]; } H;
#pragma unroll
        for (int j = 0; j < 8; j++) H.h[j] = __float2half_rn(xs[j]);
        *(uint4*)(a_act[z] + base) = H.u4;
    } else {
        const int kk = blockIdx.x;
        if (kk >= 1024) return;
        const int w = z - 3;
        const float* W = (w == 0) ? Wq : (w == 1) ? Wk : (w == 2) ? Wv : Wo;
        __half* hi = b_wt[w];
#pragma unroll
        for (int j = 0; j < 4; j++) {
            const int n = threadIdx.x * 4 + j;
            const size_t idx = (w < 3)
                ? ((size_t)(n >> 6) << 16) + (size_t)kk * 64 + (n & 63)
                : (size_t)kk * 1024 + n;
            hi[(size_t)n * 1024 + kk] = __float2half_rn(W[idx]);
        }
    }
}

// V transpose: att_v [bh][s][64] fp16 -> att_vt [bh][hd][s] fp16
__global__ __launch_bounds__(256)
void conv_attn_v_kernel()
{
    __shared__ __half vs[64][68];
    const int bh = blockIdx.y, st = blockIdx.x, t = threadIdx.x;
    const size_t base = ((size_t)bh * 2048 + st * 64) * 64;

    for (int u = t; u < 512; u += 256) {
        const int s = u >> 3, hd = (u & 7) * 8;
        union { uint4 u4; __half h[8]; } H;
        H.u4 = *(const uint4*)(att_v + base + (size_t)s * 64 + hd);
#pragma unroll
        for (int j = 0; j < 8; j++) vs[s][hd + j] = H.h[j];
    }
    __syncthreads();
    for (int u = t; u < 512; u += 256) {
        const int hd = u >> 3, s0 = (u & 7) * 8;
        union { uint4 u4; __half h[8]; } H;
#pragma unroll
        for (int j = 0; j < 8; j++) H.h[j] = vs[s0 + j][hd];
        const size_t o = ((size_t)bh * 64 + hd) * 2048 + st * 64 + s0;
        *(uint4*)(att_vt + o) = H.u4;
    }
}

// ---------------------------------------------------------------------------
// mma.sync fp16 GEMM. PASSES: 1 = A hi only, 2 = A hi+lo.
// MODE: 0 = att_q fp16, 1 = att_k fp16 xKSCL, 2 = att_v fp16, 3 = fp32 out.
// ---------------------------------------------------------------------------
template<int MODE, int PASSES>
__device__ __forceinline__ void gemm_core(const __half* __restrict__ At,
                                          const __half* __restrict__ Bt,
                                          const float* __restrict__ bias,
                                          float* __restrict__ C,
                                          int mt, int nt)
{
    __shared__ __align__(16) __half As[2][128][40];
    __shared__ __align__(16) __half Bs[2][128][40];

    const int tid = threadIdx.x, lane = tid & 31, wid = tid >> 5;
    const int wm = wid & 1, wn = wid >> 1;
    constexpr int NKT = PASSES * 32;

    float acc[4][4][4] = {};

    const int ar  = tid >> 1;
    const int ac0 = (tid & 1) * 2;
    const __half* Abase = At + (size_t)(mt * 128 + ar) * 1024;
    const __half* Bbase = Bt + (size_t)(nt * 128 + ar) * 1024;

    const uint32_t sAs = smem_u32(As);
    const uint32_t sBs = smem_u32(Bs);
    const uint32_t dA = sAs + ar * 80 + ac0 * 16;
    const uint32_t dB = sBs + ar * 80 + ac0 * 16;

    const uint32_t a_row = wm * 64 + (lane & 15);
    const uint32_t a_col = (lane >> 4) << 3;
    const uint32_t b_row = wn * 32 + (lane & 7) + ((lane >> 4) << 3);
    const uint32_t b_col = ((lane >> 3) & 1) << 3;

#define ISSUE(kt) do {                                                        \
    const int _kt = (kt);                                                     \
    const int _seg = _kt >> 5, _kk = _kt & 31;                                \
    const __half* _a = Abase + (size_t)_seg * 4096 * 1024 + _kk * 32 + ac0 * 8; \
    const __half* _b = Bbase + _kk * 32 + ac0 * 8;                            \
    const uint32_t _da = dA + (_kt & 1) * 10240;                              \
    const uint32_t _db = dB + (_kt & 1) * 10240;                              \
    CP16(_da, _a); CP16(_da + 16, _a + 8);                                    \
    CP16(_db, _b); CP16(_db + 16, _b + 8);                                    \
    CP_COMMIT();                                                              \
} while (0)

    ISSUE(0);
    ISSUE(1);

    for (int kt = 0; kt < NKT; kt++) {
        CP_WAIT1();
        __syncthreads();

        const uint32_t sa = sAs + (kt & 1) * 10240;
        const uint32_t sb = sBs + (kt & 1) * 10240;
#pragma unroll
        for (int ks = 0; ks < 32; ks += 16) {
            uint32_t af[4][4], bf[2][4];
#pragma unroll
            for (int mi = 0; mi < 4; mi++)
                ldsm4(af[mi], sa + ((a_row + mi * 16) * 40 + ks + a_col) * 2);
#pragma unroll
            for (int nj2 = 0; nj2 < 2; nj2++)
                ldsm4(bf[nj2], sb + ((b_row + nj2 * 16) * 40 + ks + b_col) * 2);
#pragma unroll
            for (int mi = 0; mi < 4; mi++)
#pragma unroll
                for (int nj = 0; nj < 4; nj++)
                    mma16816(acc[mi][nj], af[mi], &bf[nj >> 1][(nj & 1) * 2]);
        }
        __syncthreads();

        if (kt + 2 < NKT) ISSUE(kt + 2);
        else CP_COMMIT();
    }
#undef ISSUE

#pragma unroll
    for (int mi = 0; mi < 4; mi++) {
        const int r0 = mt * 128 + wm * 64 + mi * 16 + (lane >> 2);
#pragma unroll
        for (int nj = 0; nj < 4; nj++) {
            const int col = nt * 128 + wn * 32 + nj * 8 + ((lane & 3) << 1);
            const float b0 = bias[col], b1 = bias[col + 1];
            float c0 = acc[mi][nj][0] + b0, c1 = acc[mi][nj][1] + b1;
            float c2 = acc[mi][nj][2] + b0, c3 = acc[mi][nj][3] + b1;
            if (MODE == 1) { c0 *= KSCL; c1 *= KSCL; c2 *= KSCL; c3 *= KSCL; }
            if (MODE <= 2) {
                __half* D = (MODE == 0) ? att_q : (MODE == 1) ? att_k : att_v;
                const int h = col >> 6, hd = col & 63;
                const int b_0 = r0 >> 11, s0 = r0 & 2047;
                const int b_1 = (r0 + 8) >> 11, s1 = (r0 + 8) & 2047;
                *(uint32_t*)(D + ((size_t)((b_0 * 16 + h) * 2048 + s0)) * 64 + hd) = packh(c0, c1);
                *(uint32_t*)(D + ((size_t)((b_1 * 16 + h) * 2048 + s1)) * 64 + hd) = packh(c2, c3);
            } else {
                *(float2*)(C + (size_t)r0 * 1024 + col) = {c0, c1};
                *(float2*)(C + (size_t)(r0 + 8) * 1024 + col) = {c2, c3};
            }
        }
    }
}

__global__ __launch_bounds__(256, 2)
void qkv_gemm_kernel(const float* __restrict__ bq, const float* __restrict__ bk,
                     const float* __restrict__ bv)
{
    const int z = blockIdx.z;
    if (z == 0)      gemm_core<0, 1>(a_act[0], b_wt[0], bq, nullptr, blockIdx.y, blockIdx.x);
    else if (z == 1) gemm_core<1, 1>(a_act[1], b_wt[1], bk, nullptr, blockIdx.y, blockIdx.x);
    else             gemm_core<2, 1>(a_act[2], b_wt[2], bv, nullptr, blockIdx.y, blockIdx.x);
}

__global__ __launch_bounds__(256, 2)
void oproj_gemm_kernel(const float* __restrict__ bo, float* __restrict__ out)
{
    gemm_core<3, 1>(a_act[3], b_wt[3], bo, out, blockIdx.y, blockIdx.x);
}

// ---------------------------------------------------------------------------
// Tensor-core flash attention, v7: single-pass fp16, exp2-domain softmax
// (scale*log2e folded into K), ctx written hi-only.
// Grid (8 q-tiles, 32 bh), 256 threads (8 warps), warp = 32 Q rows.
// ---------------------------------------------------------------------------
constexpr int ATW = 72;
constexpr int ATT_SMEM = 2 * 2 * 64 * ATW * 2;            // 36864 B

__global__ __launch_bounds__(256, 1)
void attn_tc_kernel()
{
    extern __shared__ __half smb[];
    const uint32_t sb = smem_u32(smb);
    const int tid = threadIdx.x, lane = tid & 31, w = tid >> 5;
    const int bh = blockIdx.y;
    const int q0 = blockIdx.x * 256;

    // ---- Q fragments, staged through smem ----
    uint32_t qh[2][4][4];
    {
        const int chunk = w >> 2;
        const int wrow  = (w & 3) * 32;
#pragma unroll
        for (int c = 0; c < 2; c++) {
            const __half* src = att_q + ((size_t)bh * 2048 + q0 + c * 128) * 64;
            for (int u = tid; u < 1024; u += 256) {
                const int r = u >> 3, col = (u & 7) * 8;
                *(uint4*)(smb + r * ATW + col) = *(const uint4*)(src + (size_t)r * 64 + col);
            }
            __syncthreads();
            if (chunk == c) {
#pragma unroll
                for (int mi = 0; mi < 2; mi++) {
                    const uint32_t ab = sb +
                        (((wrow + mi * 16 + (lane & 15)) * ATW + ((lane >> 4) << 3)) << 1);
#pragma unroll
                    for (int kk = 0; kk < 4; kk++)
                        ldsm4(qh[mi][kk], ab + kk * 32);
                }
            }
            __syncthreads();
        }
    }

    // ---- KV pipeline ----
    const int arr = tid >> 7;              // 0:KH 1:VH
    const int rr0 = (tid >> 1) & 63;
    const int hf  = tid & 1;
    const __half* src0;
    size_t step;
    if (arr == 0) { src0 = att_k  + ((size_t)bh * 2048 + rr0) * 64 + hf * 32;  step = 4096; }
    else          { src0 = att_vt + ((size_t)bh * 64 + rr0) * 2048 + hf * 32;  step = 64;   }
    const uint32_t dst0 = sb + arr * 9216 + rr0 * 144 + hf * 64;

#define AISSUE(it) do {                                                       \
    const __half* _s = src0 + (size_t)(it) * step;                            \
    const uint32_t _d = dst0 + ((it) & 1) * 18432;                            \
    CP16(_d, _s); CP16(_d + 16, _s + 8);                                      \
    CP16(_d + 32, _s + 16); CP16(_d + 48, _s + 24);                           \
    CP_COMMIT();                                                              \
} while (0)

    AISSUE(0);
    AISSUE(1);

    const uint32_t brow  = (lane & 7) + ((lane >> 4) << 3);
    const uint32_t bcol2 = (((lane >> 3) & 1) << 3) * 2;
    const uint32_t boff  = brow * 144 + bcol2;

    float o[2][8][4] = {};
    float m[2][2], l[2][2];
#pragma unroll
    for (int mi = 0; mi < 2; mi++) { m[mi][0] = m[mi][1] = -1e30f; l[mi][0] = l[mi][1] = 0.0f; }

    for (int it = 0; it < 32; it++) {
        CP_WAIT1();
        __syncthreads();

        const uint32_t bufb = sb + (it & 1) * 18432;
        const uint32_t KH = bufb, VH = bufb + 9216;

        // ---- S = qh * KH (scores already in log2 domain) ----
        float s[2][8][4] = {};
        {
            uint32_t bfb[2][4];
            ldsm4(bfb[0], KH + boff);
#pragma unroll
            for (int i = 0; i < 16; i++) {
                if (i + 1 < 16) {
                    const int j = i + 1, jk = j >> 2, jg = j & 3;
                    ldsm4(bfb[j & 1], KH + (jg * 16) * 144 + jk * 32 + boff);
                }
                const uint32_t* bf = bfb[i & 1];
                const int kk = i >> 2, g = i & 3;
#pragma unroll
                for (int mi = 0; mi < 2; mi++) {
                    mma16816(s[mi][2 * g],     qh[mi][kk], bf);
                    mma16816(s[mi][2 * g + 1], qh[mi][kk], bf + 2);
                }
            }
        }

        // Prefetch first V fragment; latency hides behind softmax.
        uint32_t bfv[2][4];
        ldsm4(bfv[0], VH + boff);

        // ---- online softmax (exp2 domain); l from fp16-ROUNDED p ----
        uint32_t ph[2][4][4];
#pragma unroll
        for (int mi = 0; mi < 2; mi++) {
            float mx0 = -1e30f, mx1 = -1e30f;
#pragma unroll
            for (int nj = 0; nj < 8; nj++) {
                mx0 = fmaxf(mx0, fmaxf(s[mi][nj][0], s[mi][nj][1]));
                mx1 = fmaxf(mx1, fmaxf(s[mi][nj][2], s[mi][nj][3]));
            }
            mx0 = fmaxf(mx0, __shfl_xor_sync(0xffffffffu, mx0, 1));
            mx0 = fmaxf(mx0, __shfl_xor_sync(0xffffffffu, mx0, 2));
            mx1 = fmaxf(mx1, __shfl_xor_sync(0xffffffffu, mx1, 1));
            mx1 = fmaxf(mx1, __shfl_xor_sync(0xffffffffu, mx1, 2));
            const float mn0 = fmaxf(m[mi][0], mx0), mn1 = fmaxf(m[mi][1], mx1);
            const float f0 = fexp2(m[mi][0] - mn0), f1 = fexp2(m[mi][1] - mn1);
            m[mi][0] = mn0; m[mi][1] = mn1;

            float la0 = 0.0f, la1 = 0.0f;
#pragma unroll
            for (int nj = 0; nj < 8; nj++) {
                const float p0 = fexp2(s[mi][nj][0] - mn0);
                const float p1 = fexp2(s[mi][nj][1] - mn0);
                const float p2 = fexp2(s[mi][nj][2] - mn1);
                const float p3 = fexp2(s[mi][nj][3] - mn1);
                const uint32_t u01 = packh(p0, p1);
                const uint32_t u23 = packh(p2, p3);
                const __half2 h01 = *(const __half2*)&u01;
                const __half2 h23 = *(const __half2*)&u23;
                la0 += __half2float(h01.x) + __half2float(h01.y);
                la1 += __half2float(h23.x) + __half2float(h23.y);
                const int kk = nj >> 1, sel = (nj & 1) * 2;
                ph[mi][kk][sel]     = u01;
                ph[mi][kk][sel + 1] = u23;
            }
            la0 += __shfl_xor_sync(0xffffffffu, la0, 1);
            la0 += __shfl_xor_sync(0xffffffffu, la0, 2);
            la1 += __shfl_xor_sync(0xffffffffu, la1, 1);
            la1 += __shfl_xor_sync(0xffffffffu, la1, 2);
            l[mi][0] = l[mi][0] * f0 + la0;
            l[mi][1] = l[mi][1] * f1 + la1;
#pragma unroll
            for (int nj = 0; nj < 8; nj++) {
                o[mi][nj][0] *= f0; o[mi][nj][1] *= f0;
                o[mi][nj][2] *= f1; o[mi][nj][3] *= f1;
            }
        }

        // ---- O += ph * VH ----
#pragma unroll
        for (int i = 0; i < 16; i++) {
            if (i + 1 < 16) {
                const int j = i + 1, jk = j >> 2, jg = j & 3;
                ldsm4(bfv[j & 1], VH + (jg * 16) * 144 + jk * 32 + boff);
            }
            const uint32_t* bf = bfv[i & 1];
            const int kk = i >> 2, g = i & 3;
#pragma unroll
            for (int mi = 0; mi < 2; mi++) {
                mma16816(o[mi][2 * g],     ph[mi][kk], bf);
                mma16816(o[mi][2 * g + 1], ph[mi][kk], bf + 2);
            }
        }

        __syncthreads();
        if (it + 2 < 32) AISSUE(it + 2);
        else CP_COMMIT();
    }
#undef AISSUE

    // ---- epilogue: write ctx (hi only) into a_act[3] ----
    const int b = bh >> 4, h = bh & 15;
    __half* HI = a_act[3];
#pragma unroll
    for (int mi = 0; mi < 2; mi++) {
        const float inv0 = 1.0f / l[mi][0], inv1 = 1.0f / l[mi][1];
        const int row0 = b * 2048 + q0 + w * 32 + mi * 16 + (lane >> 2);
#pragma unroll
        for (int nj = 0; nj < 8; nj++) {
            const int col = h * 64 + nj * 8 + ((lane & 3) << 1);
            *(uint32_t*)(HI + (size_t)row0 * 1024 + col) =
                packh(o[mi][nj][0] * inv0, o[mi][nj][1] * inv0);
            *(uint32_t*)(HI + (size_t)(row0 + 8) * 1024 + col) =
                packh(o[mi][nj][2] * inv1, o[mi][nj][3] * inv1);
        }
    }
}

// ---------------------------------------------------------------------------
extern "C" void kernel_launch(void* const* d_in, const int* in_sizes, int n_in,
                              void* d_out, int out_size)
{
    (void)in_sizes; (void)n_in; (void)out_size;
    const float* q  = (const float*)d_in[0];
    const float* k  = (const float*)d_in[1];
    const float* v  = (const float*)d_in[2];
    const float* Wq = (const float*)d_in[3];
    const float* bq = (const float*)d_in[4];
    const float* Wk = (const float*)d_in[5];
    const float* bk = (const float*)d_in[6];
    const float* Wv = (const float*)d_in[7];
    const float* bv = (const float*)d_in[8];
    const float* Wo = (const float*)d_in[9];
    const float* bo = (const float*)d_in[10];
    float* out = (float*)d_out;

    cudaFuncSetAttribute(attn_tc_kernel, cudaFuncAttributeMaxDynamicSharedMemorySize,
                         ATT_SMEM);

    // All input conversions in one launch
    conv_all_kernel<<<dim3(2048, 1, 7), 256>>>(q, k, v, Wq, Wk, Wv, Wo);

    // QKV projections -> att_q / att_k (xKSCL) / att_v, all fp16
    qkv_gemm_kernel<<<dim3(8, 32, 3), 256>>>(bq, bk, bv);

    // V transpose + tensor-core flash attention (exp2 softmax)
    conv_attn_v_kernel<<<dim3(32, 32), 256>>>();
    attn_tc_kernel<<<dim3(8, 32), 256, ATT_SMEM>>>();

    // Output projection (1-pass)
    oproj_gemm_kernel<<<dim3(8, 32), 256>>>(bo, out);
}

// round 11
// speedup vs baseline: 4.6014x; 1.1566x over previous
#include <cuda_runtime.h>
#include <cuda_fp16.h>
#include <cstdint>

// Problem constants
constexpr int Bb  = 2;
constexpr int Ss  = 2048;
constexpr int Dd  = 1024;
constexpr int Hh  = 16;
constexpr int HDd = 64;

// 0.125 * log2(e): folds softmax scale AND exp->exp2 conversion into K.
#define KSCL 0.1803368801111204f

// ---------------------------------------------------------------------------
// Scratch (allocation-free: __device__ globals)
// ---------------------------------------------------------------------------
__device__ __half a_act[4][2 * 4096 * 1024];   // a_act[3] = ctx (hi only)
__device__ __half b_wt[4][1024 * 1024];

__device__ __half att_q[(size_t)32 * 2048 * 64];      // [bh][s][hd]
__device__ __half att_k[(size_t)32 * 2048 * 64];      // [bh][s][hd], x KSCL
__device__ __half att_v[(size_t)32 * 2048 * 64];      // [bh][s][hd]
__device__ __half att_vt[(size_t)32 * 64 * 2048];     // [bh][hd][s]

// ---------------------------------------------------------------------------
// Helpers
// ---------------------------------------------------------------------------
__device__ __forceinline__ uint32_t smem_u32(const void* p) {
    uint32_t a;
    asm("{ .reg .u64 t; cvta.to.shared.u64 t, %1; cvt.u32.u64 %0, t; }"
        : "=r"(a) : "l"(p));
    return a;
}

#define CP16(dst, src) \
    asm volatile("cp.async.cg.shared.global [%0], [%1], 16;" :: "r"(dst), "l"(src))
#define CP_COMMIT() asm volatile("cp.async.commit_group;" ::: "memory")
#define CP_WAIT1()  asm volatile("cp.async.wait_group 1;" ::: "memory")

__device__ __forceinline__ void ldsm4(uint32_t* r, uint32_t addr) {
    asm volatile("ldmatrix.sync.aligned.m8n8.x4.shared.b16 {%0,%1,%2,%3}, [%4];"
        : "=r"(r[0]), "=r"(r[1]), "=r"(r[2]), "=r"(r[3]) : "r"(addr));
}

__device__ __forceinline__ void mma16816(float* c, const uint32_t* a, const uint32_t* b) {
    asm volatile(
        "mma.sync.aligned.m16n8k16.row.col.f32.f16.f16.f32 "
        "{%0,%1,%2,%3}, {%4,%5,%6,%7}, {%8,%9}, {%0,%1,%2,%3};"
        : "+f"(c[0]), "+f"(c[1]), "+f"(c[2]), "+f"(c[3])
        : "r"(a[0]), "r"(a[1]), "r"(a[2]), "r"(a[3]), "r"(b[0]), "r"(b[1]));
}

__device__ __forceinline__ uint32_t packh(float x, float y) {
    __half2 t = __floats2half2_rn(x, y);
    return *(uint32_t*)&t;
}

__device__ __forceinline__ float fexp2(float x) {
    float r;
    asm("ex2.approx.f32 %0, %1;" : "=f"(r) : "f"(x));
    return r;
}

// ---------------------------------------------------------------------------
// Fused conversion kernel (same as R10)
// ---------------------------------------------------------------------------
__global__ __launch_bounds__(256)
void conv_all_kernel(const float* __restrict__ q, const float* __restrict__ k,
                     const float* __restrict__ v,
                     const float* __restrict__ Wq, const float* __restrict__ Wk,
                     const float* __restrict__ Wv, const float* __restrict__ Wo)
{
    const int z = blockIdx.z;
    if (z < 3) {
        const float* src = (z == 0) ? q : (z == 1) ? k : v;
        const size_t base = ((size_t)blockIdx.x * 256 + threadIdx.x) * 8;
        float4 f0 = *(const float4*)(src + base);
        float4 f1 = *(const float4*)(src + base + 4);
        float xs[8] = {f0.x, f0.y, f0.z, f0.w, f1.x, f1.y, f1.z, f1.w};
        union { uint4 u4; __half h[8]; } H;
#pragma unroll
        for (int j = 0; j < 8; j++) H.h[j] = __float2half_rn(xs[j]);
        *(uint4*)(a_act[z] + base) = H.u4;
    } else {
        const int kk = blockIdx.x;
        if (kk >= 1024) return;
        const int w = z - 3;
        const float* W = (w == 0) ? Wq : (w == 1) ? Wk : (w == 2) ? Wv : Wo;
        __half* hi = b_wt[w];
#pragma unroll
        for (int j = 0; j < 4; j++) {
            const int n = threadIdx.x * 4 + j;
            const size_t idx = (w < 3)
                ? ((size_t)(n >> 6) << 16) + (size_t)kk * 64 + (n & 63)
                : (size_t)kk * 1024 + n;
            hi[(size_t)n * 1024 + kk] = __float2half_rn(W[idx]);
        }
    }
}

// V transpose: att_v [bh][s][64] -> att_vt [bh][hd][s]
__global__ __launch_bounds__(256)
void conv_attn_v_kernel()
{
    __shared__ __half vs[64][68];
    const int bh = blockIdx.y, st = blockIdx.x, t = threadIdx.x;
    const size_t base = ((size_t)bh * 2048 + st * 64) * 64;

    for (int u = t; u < 512; u += 256) {
        const int s = u >> 3, hd = (u & 7) * 8;
        union { uint4 u4; __half h[8]; } H;
        H.u4 = *(const uint4*)(att_v + base + (size_t)s * 64 + hd);
#pragma unroll
        for (int j = 0; j < 8; j++) vs[s][hd + j] = H.h[j];
    }
    __syncthreads();
    for (int u = t; u < 512; u += 256) {
        const int hd = u >> 3, s0 = (u & 7) * 8;
        union { uint4 u4; __half h[8]; } H;
#pragma unroll
        for (int j = 0; j < 8; j++) H.h[j] = vs[s0 + j][hd];
        const size_t o = ((size_t)bh * 64 + hd) * 2048 + st * 64 + s0;
        *(uint4*)(att_vt + o) = H.u4;
    }
}

// ---------------------------------------------------------------------------
// mma.sync fp16 GEMM, 3-stage cp.async pipeline, ONE syncthreads per kt.
// Dynamic smem: As 3 stages @ 10240 B, then Bs 3 stages @ 10240 B = 61440 B.
// MODE: 0 = att_q, 1 = att_k xKSCL, 2 = att_v, 3 = fp32 out.
// ---------------------------------------------------------------------------
constexpr int GEMM_SMEM = 61440;

template<int MODE>
__device__ __forceinline__ void gemm_core(const __half* __restrict__ At,
                                          const __half* __restrict__ Bt,
                                          const float* __restrict__ bias,
                                          float* __restrict__ C,
                                          int mt, int nt)
{
    extern __shared__ __align__(16) char gsm[];

    const int tid = threadIdx.x, lane = tid & 31, wid = tid >> 5;
    const int wm = wid & 1, wn = wid >> 1;
    constexpr int NKT = 32;

    float acc[4][4][4] = {};

    const int ar  = tid >> 1;
    const int ac0 = (tid & 1) * 2;
    const __half* Abase = At + (size_t)(mt * 128 + ar) * 1024;
    const __half* Bbase = Bt + (size_t)(nt * 128 + ar) * 1024;

    const uint32_t sAs = smem_u32(gsm);
    const uint32_t sBs = sAs + 30720;
    const uint32_t dA = sAs + ar * 80 + ac0 * 16;
    const uint32_t dB = sBs + ar * 80 + ac0 * 16;

    const uint32_t a_row = wm * 64 + (lane & 15);
    const uint32_t a_col = (lane >> 4) << 3;
    const uint32_t b_row = wn * 32 + (lane & 7) + ((lane >> 4) << 3);
    const uint32_t b_col = ((lane >> 3) & 1) << 3;

#define ISSUE(kt, stg) do {                                                   \
    const int _kk = (kt);                                                     \
    const __half* _a = Abase + _kk * 32 + ac0 * 8;                            \
    const __half* _b = Bbase + _kk * 32 + ac0 * 8;                            \
    const uint32_t _da = dA + (stg) * 10240;                                  \
    const uint32_t _db = dB + (stg) * 10240;                                  \
    CP16(_da, _a); CP16(_da + 16, _a + 8);                                    \
    CP16(_db, _b); CP16(_db + 16, _b + 8);                                    \
    CP_COMMIT();                                                              \
} while (0)

    ISSUE(0, 0);
    ISSUE(1, 1);

    int rs = 0, ws = 2;
    for (int kt = 0; kt < NKT; kt++) {
        CP_WAIT1();
        __syncthreads();
        if (kt + 2 < NKT) ISSUE(kt + 2, ws);
        else CP_COMMIT();

        const uint32_t sa = sAs + rs * 10240;
        const uint32_t sb = sBs + rs * 10240;
#pragma unroll
        for (int ks = 0; ks < 32; ks += 16) {
            uint32_t af[4][4], bf[2][4];
#pragma unroll
            for (int mi = 0; mi < 4; mi++)
                ldsm4(af[mi], sa + ((a_row + mi * 16) * 40 + ks + a_col) * 2);
#pragma unroll
            for (int nj2 = 0; nj2 < 2; nj2++)
                ldsm4(bf[nj2], sb + ((b_row + nj2 * 16) * 40 + ks + b_col) * 2);
#pragma unroll
            for (int mi = 0; mi < 4; mi++)
#pragma unroll
                for (int nj = 0; nj < 4; nj++)
                    mma16816(acc[mi][nj], af[mi], &bf[nj >> 1][(nj & 1) * 2]);
        }
        rs = (rs == 2) ? 0 : rs + 1;
        ws = (ws == 2) ? 0 : ws + 1;
    }
#undef ISSUE

#pragma unroll
    for (int mi = 0; mi < 4; mi++) {
        const int r0 = mt * 128 + wm * 64 + mi * 16 + (lane >> 2);
#pragma unroll
        for (int nj = 0; nj < 4; nj++) {
            const int col = nt * 128 + wn * 32 + nj * 8 + ((lane & 3) << 1);
            const float b0 = bias[col], b1 = bias[col + 1];
            float c0 = acc[mi][nj][0] + b0, c1 = acc[mi][nj][1] + b1;
            float c2 = acc[mi][nj][2] + b0, c3 = acc[mi][nj][3] + b1;
            if (MODE == 1) { c0 *= KSCL; c1 *= KSCL; c2 *= KSCL; c3 *= KSCL; }
            if (MODE <= 2) {
                __half* D = (MODE == 0) ? att_q : (MODE == 1) ? att_k : att_v;
                const int h = col >> 6, hd = col & 63;
                const int b_0 = r0 >> 11, s0 = r0 & 2047;
                const int b_1 = (r0 + 8) >> 11, s1 = (r0 + 8) & 2047;
                *(uint32_t*)(D + ((size_t)((b_0 * 16 + h) * 2048 + s0)) * 64 + hd) = packh(c0, c1);
                *(uint32_t*)(D + ((size_t)((b_1 * 16 + h) * 2048 + s1)) * 64 + hd) = packh(c2, c3);
            } else {
                *(float2*)(C + (size_t)r0 * 1024 + col) = {c0, c1};
                *(float2*)(C + (size_t)(r0 + 8) * 1024 + col) = {c2, c3};
            }
        }
    }
}

__global__ __launch_bounds__(256, 2)
void qkv_gemm_kernel(const float* __restrict__ bq, const float* __restrict__ bk,
                     const float* __restrict__ bv)
{
    const int z = blockIdx.z;
    if (z == 0)      gemm_core<0>(a_act[0], b_wt[0], bq, nullptr, blockIdx.y, blockIdx.x);
    else if (z == 1) gemm_core<1>(a_act[1], b_wt[1], bk, nullptr, blockIdx.y, blockIdx.x);
    else             gemm_core<2>(a_act[2], b_wt[2], bv, nullptr, blockIdx.y, blockIdx.x);
}

__global__ __launch_bounds__(256, 2)
void oproj_gemm_kernel(const float* __restrict__ bo, float* __restrict__ out)
{
    gemm_core<3>(a_act[3], b_wt[3], bo, out, blockIdx.y, blockIdx.x);
}

// ---------------------------------------------------------------------------
// Tensor-core flash attention, v8: f16x2 exp2, lazy l-reduction, 3-stage
// pipeline with one syncthreads per iteration.
// Grid (8 q-tiles, 32 bh), 256 threads (8 warps), warp = 32 Q rows.
// Dynamic smem: 3 stages x (KH 9216 + VH 9216) = 55296 B.
// ---------------------------------------------------------------------------
constexpr int ATW = 72;
constexpr int ATT_SMEM = 3 * 18432;

__global__ __launch_bounds__(256, 1)
void attn_tc_kernel()
{
    extern __shared__ __half smb[];
    const uint32_t sb = smem_u32(smb);
    const int tid = threadIdx.x, lane = tid & 31, w = tid >> 5;
    const int bh = blockIdx.y;
    const int q0 = blockIdx.x * 256;

    // ---- Q fragments, staged through smem (before pipeline starts) ----
    uint32_t qh[2][4][4];
    {
        const int chunk = w >> 2;
        const int wrow  = (w & 3) * 32;
#pragma unroll
        for (int c = 0; c < 2; c++) {
            const __half* src = att_q + ((size_t)bh * 2048 + q0 + c * 128) * 64;
            for (int u = tid; u < 1024; u += 256) {
                const int r = u >> 3, col = (u & 7) * 8;
                *(uint4*)(smb + r * ATW + col) = *(const uint4*)(src + (size_t)r * 64 + col);
            }
            __syncthreads();
            if (chunk == c) {
#pragma unroll
                for (int mi = 0; mi < 2; mi++) {
                    const uint32_t ab = sb +
                        (((wrow + mi * 16 + (lane & 15)) * ATW + ((lane >> 4) << 3)) << 1);
#pragma unroll
                    for (int kk = 0; kk < 4; kk++)
                        ldsm4(qh[mi][kk], ab + kk * 32);
                }
            }
            __syncthreads();
        }
    }

    // ---- KV pipeline ----
    const int arr = tid >> 7;              // 0:KH 1:VH
    const int rr0 = (tid >> 1) & 63;
    const int hf  = tid & 1;
    const __half* src0;
    size_t step;
    if (arr == 0) { src0 = att_k  + ((size_t)bh * 2048 + rr0) * 64 + hf * 32;  step = 4096; }
    else          { src0 = att_vt + ((size_t)bh * 64 + rr0) * 2048 + hf * 32;  step = 64;   }
    const uint32_t dst0 = sb + arr * 9216 + rr0 * 144 + hf * 64;

#define AISSUE(it, stg) do {                                                  \
    const __half* _s = src0 + (size_t)(it) * step;                            \
    const uint32_t _d = dst0 + (stg) * 18432;                                 \
    CP16(_d, _s); CP16(_d + 16, _s + 8);                                      \
    CP16(_d + 32, _s + 16); CP16(_d + 48, _s + 24);                           \
    CP_COMMIT();                                                              \
} while (0)

    AISSUE(0, 0);
    AISSUE(1, 1);

    const uint32_t brow  = (lane & 7) + ((lane >> 4) << 3);
    const uint32_t bcol2 = (((lane >> 3) & 1) << 3) * 2;
    const uint32_t boff  = brow * 144 + bcol2;

    float o[2][8][4] = {};
    float m[2][2], l[2][2];
#pragma unroll
    for (int mi = 0; mi < 2; mi++) { m[mi][0] = m[mi][1] = -1e30f; l[mi][0] = l[mi][1] = 0.0f; }

    int rs = 0, ws = 2;
    for (int it = 0; it < 32; it++) {
        CP_WAIT1();
        __syncthreads();
        if (it + 2 < 32) AISSUE(it + 2, ws);
        else CP_COMMIT();

        const uint32_t bufb = sb + rs * 18432;
        const uint32_t KH = bufb, VH = bufb + 9216;

        // ---- S = qh * KH (log2-domain scores) ----
        float s[2][8][4] = {};
        {
            uint32_t bfb[2][4];
            ldsm4(bfb[0], KH + boff);
#pragma unroll
            for (int i = 0; i < 16; i++) {
                if (i + 1 < 16) {
                    const int j = i + 1, jk = j >> 2, jg = j & 3;
                    ldsm4(bfb[j & 1], KH + (jg * 16) * 144 + jk * 32 + boff);
                }
                const uint32_t* bf = bfb[i & 1];
                const int kk = i >> 2, g = i & 3;
#pragma unroll
                for (int mi = 0; mi < 2; mi++) {
                    mma16816(s[mi][2 * g],     qh[mi][kk], bf);
                    mma16816(s[mi][2 * g + 1], qh[mi][kk], bf + 2);
                }
            }
        }

        // Prefetch first V fragment; latency hides behind softmax.
        uint32_t bfv[2][4];
        ldsm4(bfv[0], VH + boff);

        // ---- online softmax: f16x2 exp2; l kept as per-thread partial ----
        uint32_t ph[2][4][4];
#pragma unroll
        for (int mi = 0; mi < 2; mi++) {
            float mx0 = -1e30f, mx1 = -1e30f;
#pragma unroll
            for (int nj = 0; nj < 8; nj++) {
                mx0 = fmaxf(mx0, fmaxf(s[mi][nj][0], s[mi][nj][1]));
                mx1 = fmaxf(mx1, fmaxf(s[mi][nj][2], s[mi][nj][3]));
            }
            mx0 = fmaxf(mx0, __shfl_xor_sync(0xffffffffu, mx0, 1));
            mx0 = fmaxf(mx0, __shfl_xor_sync(0xffffffffu, mx0, 2));
            mx1 = fmaxf(mx1, __shfl_xor_sync(0xffffffffu, mx1, 1));
            mx1 = fmaxf(mx1, __shfl_xor_sync(0xffffffffu, mx1, 2));
            const float mn0 = fmaxf(m[mi][0], mx0), mn1 = fmaxf(m[mi][1], mx1);
            const float f0 = fexp2(m[mi][0] - mn0), f1 = fexp2(m[mi][1] - mn1);
            m[mi][0] = mn0; m[mi][1] = mn1;

            float la0 = 0.0f, la1 = 0.0f;
#pragma unroll
            for (int nj = 0; nj < 8; nj++) {
                uint32_t u01 = packh(s[mi][nj][0] - mn0, s[mi][nj][1] - mn0);
                uint32_t u23 = packh(s[mi][nj][2] - mn1, s[mi][nj][3] - mn1);
                asm("ex2.approx.f16x2 %0, %0;" : "+r"(u01));
                asm("ex2.approx.f16x2 %0, %0;" : "+r"(u23));
                const float2 f01 = __half22float2(*(const __half2*)&u01);
                const float2 f23 = __half22float2(*(const __half2*)&u23);
                la0 += f01.x + f01.y;
                la1 += f23.x + f23.y;
                const int kk = nj >> 1, sel = (nj & 1) * 2;
                ph[mi][kk][sel]     = u01;
                ph[mi][kk][sel + 1] = u23;
            }
            // per-thread partial l (quad-reduced once in the epilogue)
            l[mi][0] = l[mi][0] * f0 + la0;
            l[mi][1] = l[mi][1] * f1 + la1;
#pragma unroll
            for (int nj = 0; nj < 8; nj++) {
                o[mi][nj][0] *= f0; o[mi][nj][1] *= f0;
                o[mi][nj][2] *= f1; o[mi][nj][3] *= f1;
            }
        }

        // ---- O += ph * VH ----
#pragma unroll
        for (int i = 0; i < 16; i++) {
            if (i + 1 < 16) {
                const int j = i + 1, jk = j >> 2, jg = j & 3;
                ldsm4(bfv[j & 1], VH + (jg * 16) * 144 + jk * 32 + boff);
            }
            const uint32_t* bf = bfv[i & 1];
            const int kk = i >> 2, g = i & 3;
#pragma unroll
            for (int mi = 0; mi < 2; mi++) {
                mma16816(o[mi][2 * g],     ph[mi][kk], bf);
                mma16816(o[mi][2 * g + 1], ph[mi][kk], bf + 2);
            }
        }

        rs = (rs == 2) ? 0 : rs + 1;
        ws = (ws == 2) ? 0 : ws + 1;
    }
#undef AISSUE

    // ---- epilogue: quad-reduce l, write ctx (hi only) into a_act[3] ----
    const int b = bh >> 4, h = bh & 15;
    __half* HI = a_act[3];
#pragma unroll
    for (int mi = 0; mi < 2; mi++) {
        float l0 = l[mi][0], l1 = l[mi][1];
        l0 += __shfl_xor_sync(0xffffffffu, l0, 1);
        l0 += __shfl_xor_sync(0xffffffffu, l0, 2);
        l1 += __shfl_xor_sync(0xffffffffu, l1, 1);
        l1 += __shfl_xor_sync(0xffffffffu, l1, 2);
        const float inv0 = 1.0f / l0, inv1 = 1.0f / l1;
        const int row0 = b * 2048 + q0 + w * 32 + mi * 16 + (lane >> 2);
#pragma unroll
        for (int nj = 0; nj < 8; nj++) {
            const int col = h * 64 + nj * 8 + ((lane & 3) << 1);
            *(uint32_t*)(HI + (size_t)row0 * 1024 + col) =
                packh(o[mi][nj][0] * inv0, o[mi][nj][1] * inv0);
            *(uint32_t*)(HI + (size_t)(row0 + 8) * 1024 + col) =
                packh(o[mi][nj][2] * inv1, o[mi][nj][3] * inv1);
        }
    }
}

// ---------------------------------------------------------------------------
extern "C" void kernel_launch(void* const* d_in, const int* in_sizes, int n_in,
                              void* d_out, int out_size)
{
    (void)in_sizes; (void)n_in; (void)out_size;
    const float* q  = (const float*)d_in[0];
    const float* k  = (const float*)d_in[1];
    const float* v  = (const float*)d_in[2];
    const float* Wq = (const float*)d_in[3];
    const float* bq = (const float*)d_in[4];
    const float* Wk = (const float*)d_in[5];
    const float* bk = (const float*)d_in[6];
    const float* Wv = (const float*)d_in[7];
    const float* bv = (const float*)d_in[8];
    const float* Wo = (const float*)d_in[9];
    const float* bo = (const float*)d_in[10];
    float* out = (float*)d_out;

    cudaFuncSetAttribute(attn_tc_kernel, cudaFuncAttributeMaxDynamicSharedMemorySize,
                         ATT_SMEM);
    cudaFuncSetAttribute(qkv_gemm_kernel, cudaFuncAttributeMaxDynamicSharedMemorySize,
                         GEMM_SMEM);
    cudaFuncSetAttribute(oproj_gemm_kernel, cudaFuncAttributeMaxDynamicSharedMemorySize,
                         GEMM_SMEM);

    conv_all_kernel<<<dim3(2048, 1, 7), 256>>>(q, k, v, Wq, Wk, Wv, Wo);

    qkv_gemm_kernel<<<dim3(8, 32, 3), 256, GEMM_SMEM>>>(bq, bk, bv);

    conv_attn_v_kernel<<<dim3(32, 32), 256>>>();
    attn_tc_kernel<<<dim3(8, 32), 256, ATT_SMEM>>>();

    oproj_gemm_kernel<<<dim3(8, 32), 256, GEMM_SMEM>>>(bo, out);
}